// round 1
// baseline (speedup 1.0000x reference)
#include <cuda_runtime.h>
#include <math.h>

#define B_    4
#define S_    2048
#define D_    1024
#define H_    16
#define DH    64
#define DFF_  512
#define P_    256
#define MROWS (B_*S_)   // 8192

// scratch: xn, q, k, v, ctx, x1, x2 (each MROWS*D_) + h (MROWS*DFF_)
#define NM ((size_t)MROWS * D_)
__device__ float g_scratch[7 * (size_t)MROWS * D_ + (size_t)MROWS * DFF_];

// ---------------------------------------------------------------------------
// Block reduce (256 threads = 8 warps)
// ---------------------------------------------------------------------------
__device__ __forceinline__ float blockReduceSum(float v, float* sbuf) {
    int lane = threadIdx.x & 31, wid = threadIdx.x >> 5;
    #pragma unroll
    for (int o = 16; o; o >>= 1) v += __shfl_xor_sync(0xffffffffu, v, o);
    if (lane == 0) sbuf[wid] = v;
    __syncthreads();
    if (wid == 0) {
        float w = (lane < 8) ? sbuf[lane] : 0.0f;
        #pragma unroll
        for (int o = 4; o; o >>= 1) w += __shfl_xor_sync(0xffffffffu, w, o);
        if (lane == 0) sbuf[0] = w;
    }
    __syncthreads();
    float r = sbuf[0];
    __syncthreads();   // allow buffer reuse
    return r;
}

// ---------------------------------------------------------------------------
// LayerNorm: torch-style, unbiased std (n-1), eps added to std
// one block per row, 256 threads, D=1024 -> 1 float4 per thread
// ---------------------------------------------------------------------------
__global__ void ln_kernel(const float* __restrict__ X,
                          const float* __restrict__ alpha,
                          const float* __restrict__ beta,
                          float* __restrict__ Y) {
    __shared__ float sbuf[8];
    size_t row = blockIdx.x;
    const float4* x4 = (const float4*)(X + row * D_);
    float4 xv = x4[threadIdx.x];
    float s = blockReduceSum(xv.x + xv.y + xv.z + xv.w, sbuf);
    float mu = s * (1.0f / D_);
    float d0 = xv.x - mu, d1 = xv.y - mu, d2 = xv.z - mu, d3 = xv.w - mu;
    float ssq = blockReduceSum(d0*d0 + d1*d1 + d2*d2 + d3*d3, sbuf);
    float inv = 1.0f / (sqrtf(ssq * (1.0f / (D_ - 1))) + 1e-6f);
    float4 a = ((const float4*)alpha)[threadIdx.x];
    float4 b = ((const float4*)beta)[threadIdx.x];
    float4 o;
    o.x = a.x * d0 * inv + b.x;
    o.y = a.y * d1 * inv + b.y;
    o.z = a.z * d2 * inv + b.z;
    o.w = a.w * d3 * inv + b.w;
    ((float4*)(Y + row * D_))[threadIdx.x] = o;
}

// ---------------------------------------------------------------------------
// Generic fp32 GEMM: C = A[MxK] @ B[KxN] (+bias) (+residual) (+accum) (relu)
// 64x64 tile, BK=16, 256 threads, 4x4 per thread.
// Requires M%64==0, N%64==0, K%16==0 (true for all call sites).
// flags: 1=relu, 2=residual (R), 4=accumulate into existing C
// ---------------------------------------------------------------------------
#define F_RELU  1
#define F_RESID 2
#define F_ACCUM 4

__global__ void gemm_kernel(const float* __restrict__ A,
                            const float* __restrict__ B,
                            const float* __restrict__ bias,
                            const float* __restrict__ R,
                            float* __restrict__ C,
                            int M, int N, int K, int flags) {
    __shared__ float As[16][64];
    __shared__ float Bs[16][64];
    int tid = threadIdx.x;
    int tx = tid & 15, ty = tid >> 4;
    int rowBase = blockIdx.y * 64, colBase = blockIdx.x * 64;

    int am = tid >> 2;          // 0..63
    int ak = (tid & 3) * 4;     // 0,4,8,12
    int bk = tid >> 4;          // 0..15
    int bn = (tid & 15) * 4;    // 0..60

    float acc[4][4] = {};

    for (int kt = 0; kt < K; kt += 16) {
        float4 av = *(const float4*)(A + (size_t)(rowBase + am) * K + kt + ak);
        As[ak + 0][am] = av.x;
        As[ak + 1][am] = av.y;
        As[ak + 2][am] = av.z;
        As[ak + 3][am] = av.w;
        float4 bv = *(const float4*)(B + (size_t)(kt + bk) * N + colBase + bn);
        *(float4*)&Bs[bk][bn] = bv;
        __syncthreads();
        #pragma unroll
        for (int k = 0; k < 16; k++) {
            float4 a = *(const float4*)&As[k][ty * 4];
            float4 b = *(const float4*)&Bs[k][tx * 4];
            acc[0][0] += a.x * b.x; acc[0][1] += a.x * b.y; acc[0][2] += a.x * b.z; acc[0][3] += a.x * b.w;
            acc[1][0] += a.y * b.x; acc[1][1] += a.y * b.y; acc[1][2] += a.y * b.z; acc[1][3] += a.y * b.w;
            acc[2][0] += a.z * b.x; acc[2][1] += a.z * b.y; acc[2][2] += a.z * b.z; acc[2][3] += a.z * b.w;
            acc[3][0] += a.w * b.x; acc[3][1] += a.w * b.y; acc[3][2] += a.w * b.z; acc[3][3] += a.w * b.w;
        }
        __syncthreads();
    }

    int c0 = colBase + tx * 4;
    float bi0 = 0.f, bi1 = 0.f, bi2 = 0.f, bi3 = 0.f;
    if (bias) { bi0 = bias[c0]; bi1 = bias[c0 + 1]; bi2 = bias[c0 + 2]; bi3 = bias[c0 + 3]; }
    #pragma unroll
    for (int i = 0; i < 4; i++) {
        size_t off = (size_t)(rowBase + ty * 4 + i) * N + c0;
        float4 res;
        res.x = acc[i][0] + bi0;
        res.y = acc[i][1] + bi1;
        res.z = acc[i][2] + bi2;
        res.w = acc[i][3] + bi3;
        if (flags & F_RESID) {
            float4 rr = *(const float4*)(R + off);
            res.x += rr.x; res.y += rr.y; res.z += rr.z; res.w += rr.w;
        }
        if (flags & F_ACCUM) {
            float4 cc = *(const float4*)(C + off);
            res.x += cc.x; res.y += cc.y; res.z += cc.z; res.w += cc.w;
        }
        if (flags & F_RELU) {
            res.x = fmaxf(res.x, 0.f); res.y = fmaxf(res.y, 0.f);
            res.z = fmaxf(res.z, 0.f); res.w = fmaxf(res.w, 0.f);
        }
        *(float4*)(C + off) = res;
    }
}

// ---------------------------------------------------------------------------
// Flash attention fp32: per (b,h), 64-query tiles, online softmax over S keys.
// dh=64. grid(S/64, B*H), 256 threads.
// Shared: Qt (Q transposed [d][q]), KtPs (K transposed, reused for P), Vs.
// ---------------------------------------------------------------------------
__global__ void flash_kernel(const float* __restrict__ Q,
                             const float* __restrict__ K,
                             const float* __restrict__ V,
                             float* __restrict__ O) {
    __shared__ float Qt[64][64];
    __shared__ float KtPs[64][64];
    __shared__ float Vs[64][64];

    int tid = threadIdx.x;
    int tx = tid & 15, ty = tid >> 4;
    int b = blockIdx.y >> 4, h = blockIdx.y & 15;
    int qbase = blockIdx.x * 64;
    const size_t base = ((size_t)b * S_) * D_ + (size_t)h * DH;

    // Load Q tile transposed: Qt[d][q]
    #pragma unroll
    for (int r = 0; r < 4; r++) {
        int qr = r * 16 + ty;
        float4 v = *(const float4*)(Q + base + (size_t)(qbase + qr) * D_ + tx * 4);
        Qt[tx * 4 + 0][qr] = v.x;
        Qt[tx * 4 + 1][qr] = v.y;
        Qt[tx * 4 + 2][qr] = v.z;
        Qt[tx * 4 + 3][qr] = v.w;
    }

    float m[4], l[4], o[4][4];
    #pragma unroll
    for (int i = 0; i < 4; i++) {
        m[i] = -1e30f; l[i] = 0.f;
        #pragma unroll
        for (int j = 0; j < 4; j++) o[i][j] = 0.f;
    }

    for (int kt = 0; kt < S_; kt += 64) {
        __syncthreads();   // prior readers of KtPs/Vs done (also guards Qt on iter 0 via next sync)
        #pragma unroll
        for (int r = 0; r < 4; r++) {
            int kr = r * 16 + ty;
            float4 kv = *(const float4*)(K + base + (size_t)(kt + kr) * D_ + tx * 4);
            KtPs[tx * 4 + 0][kr] = kv.x;
            KtPs[tx * 4 + 1][kr] = kv.y;
            KtPs[tx * 4 + 2][kr] = kv.z;
            KtPs[tx * 4 + 3][kr] = kv.w;
            float4 vv = *(const float4*)(V + base + (size_t)(kt + kr) * D_ + tx * 4);
            *(float4*)&Vs[kr][tx * 4] = vv;
        }
        __syncthreads();

        // scores s[4][4] = Q @ K^T  (q rows ty*4.., k cols tx*4..)
        float s[4][4] = {};
        #pragma unroll
        for (int d = 0; d < 64; d++) {
            float4 a = *(const float4*)&Qt[d][ty * 4];
            float4 bb = *(const float4*)&KtPs[d][tx * 4];
            s[0][0] += a.x * bb.x; s[0][1] += a.x * bb.y; s[0][2] += a.x * bb.z; s[0][3] += a.x * bb.w;
            s[1][0] += a.y * bb.x; s[1][1] += a.y * bb.y; s[1][2] += a.y * bb.z; s[1][3] += a.y * bb.w;
            s[2][0] += a.z * bb.x; s[2][1] += a.z * bb.y; s[2][2] += a.z * bb.z; s[2][3] += a.z * bb.w;
            s[3][0] += a.w * bb.x; s[3][1] += a.w * bb.y; s[3][2] += a.w * bb.z; s[3][3] += a.w * bb.w;
        }

        // online softmax per q row (reduce across the 16 tx lanes via shuffle)
        float p[4][4];
        #pragma unroll
        for (int i = 0; i < 4; i++) {
            float tm = -1e30f;
            #pragma unroll
            for (int j = 0; j < 4; j++) { s[i][j] *= 0.125f; tm = fmaxf(tm, s[i][j]); }
            #pragma unroll
            for (int off = 1; off < 16; off <<= 1)
                tm = fmaxf(tm, __shfl_xor_sync(0xffffffffu, tm, off));
            float mn = fmaxf(m[i], tm);
            float sc = __expf(m[i] - mn);
            float rs = 0.f;
            #pragma unroll
            for (int j = 0; j < 4; j++) { p[i][j] = __expf(s[i][j] - mn); rs += p[i][j]; }
            #pragma unroll
            for (int off = 1; off < 16; off <<= 1)
                rs += __shfl_xor_sync(0xffffffffu, rs, off);
            l[i] = l[i] * sc + rs;
            m[i] = mn;
            #pragma unroll
            for (int j = 0; j < 4; j++) o[i][j] *= sc;
        }

        __syncthreads();   // everyone finished reading KtPs as K
        // store P transposed into KtPs: Ps[k][q]
        #pragma unroll
        for (int i = 0; i < 4; i++)
            #pragma unroll
            for (int j = 0; j < 4; j++)
                KtPs[tx * 4 + j][ty * 4 + i] = p[i][j];
        __syncthreads();

        // O += P @ V   (q rows ty*4.., d cols tx*4..)
        const float4* Ps4 = (const float4*)KtPs;
        const float4* Vs4 = (const float4*)Vs;
        #pragma unroll
        for (int k = 0; k < 64; k++) {
            float4 pv = Ps4[k * 16 + ty];
            float4 vv = Vs4[k * 16 + tx];
            o[0][0] += pv.x * vv.x; o[0][1] += pv.x * vv.y; o[0][2] += pv.x * vv.z; o[0][3] += pv.x * vv.w;
            o[1][0] += pv.y * vv.x; o[1][1] += pv.y * vv.y; o[1][2] += pv.y * vv.z; o[1][3] += pv.y * vv.w;
            o[2][0] += pv.z * vv.x; o[2][1] += pv.z * vv.y; o[2][2] += pv.z * vv.z; o[2][3] += pv.z * vv.w;
            o[3][0] += pv.w * vv.x; o[3][1] += pv.w * vv.y; o[3][2] += pv.w * vv.z; o[3][3] += pv.w * vv.w;
        }
    }

    #pragma unroll
    for (int i = 0; i < 4; i++) {
        float inv = 1.0f / l[i];
        float4 ov;
        ov.x = o[i][0] * inv; ov.y = o[i][1] * inv;
        ov.z = o[i][2] * inv; ov.w = o[i][3] * inv;
        *(float4*)(O + base + (size_t)(qbase + ty * 4 + i) * D_ + tx * 4) = ov;
    }
}

// ---------------------------------------------------------------------------
// Launch
// ---------------------------------------------------------------------------
extern "C" void kernel_launch(void* const* d_in, const int* in_sizes, int n_in,
                              void* d_out, int out_size) {
    const float* fx  = (const float*)d_in[0];
    const float* px  = (const float*)d_in[1];
    const float* Wq  = (const float*)d_in[2];
    const float* bq  = (const float*)d_in[3];
    const float* Wk  = (const float*)d_in[4];
    const float* bk  = (const float*)d_in[5];
    const float* Wv  = (const float*)d_in[6];
    const float* bv  = (const float*)d_in[7];
    const float* Wo  = (const float*)d_in[8];
    const float* bo  = (const float*)d_in[9];
    const float* a1  = (const float*)d_in[10];
    const float* be1 = (const float*)d_in[11];
    const float* a2  = (const float*)d_in[12];
    const float* be2 = (const float*)d_in[13];
    const float* W1  = (const float*)d_in[14];
    const float* b1  = (const float*)d_in[15];
    const float* W2  = (const float*)d_in[16];
    const float* b2  = (const float*)d_in[17];
    const float* Wp  = (const float*)d_in[18];
    const float* bp  = (const float*)d_in[19];

    float* scratch = nullptr;
    cudaGetSymbolAddress((void**)&scratch, g_scratch);
    float* xn  = scratch;
    float* q   = xn  + NM;
    float* k   = q   + NM;
    float* v   = k   + NM;
    float* ctx = v   + NM;
    float* x1  = ctx + NM;
    float* x2  = x1  + NM;
    float* hh  = x2  + NM;

    float* xo = (float*)d_out;                       // (B,S,D)
    float* pp = xo + (size_t)MROWS * D_;             // (B,S,P)

    // 1. xn = LN1(feature_x)
    ln_kernel<<<MROWS, 256>>>(fx, a1, be1, xn);
    // 2-4. q/k/v
    gemm_kernel<<<dim3(D_ / 64, MROWS / 64), 256>>>(xn, Wq, bq, nullptr, q, MROWS, D_, D_, 0);
    gemm_kernel<<<dim3(D_ / 64, MROWS / 64), 256>>>(xn, Wk, bk, nullptr, k, MROWS, D_, D_, 0);
    gemm_kernel<<<dim3(D_ / 64, MROWS / 64), 256>>>(xn, Wv, bv, nullptr, v, MROWS, D_, D_, 0);
    // 5. attention
    flash_kernel<<<dim3(S_ / 64, B_ * H_), 256>>>(q, k, v, ctx);
    // 6. x1 = xn + ctx @ Wo + bo
    gemm_kernel<<<dim3(D_ / 64, MROWS / 64), 256>>>(ctx, Wo, bo, xn, x1, MROWS, D_, D_, F_RESID);
    // 7. x2 = LN2(x1)
    ln_kernel<<<MROWS, 256>>>(x1, a2, be2, x2);
    // 8. hh = relu(x2 @ W1 + b1)
    gemm_kernel<<<dim3(DFF_ / 64, MROWS / 64), 256>>>(x2, W1, b1, nullptr, hh, MROWS, DFF_, D_, F_RELU);
    // 9. x = x1 + hh @ W2 + b2  -> d_out
    gemm_kernel<<<dim3(D_ / 64, MROWS / 64), 256>>>(hh, W2, b2, x1, xo, MROWS, D_, DFF_, F_RESID);
    // 10. p = x @ Wp[0:D] + bp
    gemm_kernel<<<dim3(P_ / 64, MROWS / 64), 256>>>(xo, Wp, bp, nullptr, pp, MROWS, P_, D_, 0);
    // 11. p += param_x @ Wp[D:D+P]
    gemm_kernel<<<dim3(P_ / 64, MROWS / 64), 256>>>(px, Wp + (size_t)D_ * P_, nullptr, nullptr, pp,
                                                    MROWS, P_, P_, F_ACCUM);
}

// round 3
// speedup vs baseline: 1.3464x; 1.3464x over previous
#include <cuda_runtime.h>
#include <cuda_bf16.h>
#include <math.h>
#include <stdint.h>

#define B_    4
#define S_    2048
#define D_    1024
#define H_    16
#define DH    64
#define DFF_  512
#define P_    256
#define MROWS (B_*S_)          // 8192
#define CATW  (D_ + P_)        // 1280

#define NM  ((size_t)MROWS * D_)      // 8388608
#define NH  ((size_t)MROWS * DFF_)    // 4194304
#define NC  ((size_t)MROWS * CATW)    // 10485760

// fp32 scratch: xn, q, k, v, ctx, x1, x2 (NM each) + hh (NH)
__device__ float g_scratch[7 * NM + NH];

// bf16 scratch (hi/lo pairs)
#define OFF_XNH   ((size_t)0)
#define OFF_XNL   (OFF_XNH + NM)
#define OFF_X2H   (OFF_XNL + NM)
#define OFF_X2L   (OFF_X2H + NM)
#define OFF_CTXH  (OFF_X2L + NM)
#define OFF_CTXL  (OFF_CTXH + NM)
#define OFF_HHH   (OFF_CTXL + NM)
#define OFF_HHL   (OFF_HHH + NH)
#define OFF_CATH  (OFF_HHL + NH)
#define OFF_CATL  (OFF_CATH + NC)
#define OFF_WQH   (OFF_CATL + NC)
#define OFF_WQL   (OFF_WQH + (size_t)D_*D_)
#define OFF_WKH   (OFF_WQL + (size_t)D_*D_)
#define OFF_WKL   (OFF_WKH + (size_t)D_*D_)
#define OFF_WVH   (OFF_WKL + (size_t)D_*D_)
#define OFF_WVL   (OFF_WVH + (size_t)D_*D_)
#define OFF_WOH   (OFF_WVL + (size_t)D_*D_)
#define OFF_WOL   (OFF_WOH + (size_t)D_*D_)
#define OFF_W1H   (OFF_WOL + (size_t)D_*D_)
#define OFF_W1L   (OFF_W1H + (size_t)D_*DFF_)
#define OFF_W2H   (OFF_W1L + (size_t)D_*DFF_)
#define OFF_W2L   (OFF_W2H + (size_t)D_*DFF_)
#define OFF_WPH   (OFF_W2L + (size_t)D_*DFF_)
#define OFF_WPL   (OFF_WPH + (size_t)CATW*P_)
#define BF_TOTAL  (OFF_WPL + (size_t)CATW*P_)

__device__ __nv_bfloat16 g_bf16[BF_TOTAL];

// ---------------------------------------------------------------------------
// family-safe tensor-core primitives (sm_80+; legal on plain sm_103 target)
// ---------------------------------------------------------------------------
__device__ __forceinline__ uint32_t smem_to_u32(const void* p) {
    uint32_t a;
    asm("{ .reg .u64 t; cvta.to.shared.u64 t, %1; cvt.u32.u64 %0, t; }" : "=r"(a) : "l"(p));
    return a;
}
__device__ __forceinline__ void ldsm_x4(uint32_t* r, uint32_t addr) {
    asm volatile("ldmatrix.sync.aligned.m8n8.x4.shared.b16 {%0,%1,%2,%3}, [%4];"
                 : "=r"(r[0]), "=r"(r[1]), "=r"(r[2]), "=r"(r[3]) : "r"(addr));
}
__device__ __forceinline__ void ldsm_x2(uint32_t* r, uint32_t addr) {
    asm volatile("ldmatrix.sync.aligned.m8n8.x2.shared.b16 {%0,%1}, [%2];"
                 : "=r"(r[0]), "=r"(r[1]) : "r"(addr));
}
__device__ __forceinline__ void mma_bf16(float* c, const uint32_t* a, const uint32_t* b) {
    asm volatile(
        "mma.sync.aligned.m16n8k16.row.col.f32.bf16.bf16.f32 "
        "{%0,%1,%2,%3}, {%4,%5,%6,%7}, {%8,%9}, {%0,%1,%2,%3};"
        : "+f"(c[0]), "+f"(c[1]), "+f"(c[2]), "+f"(c[3])
        : "r"(a[0]), "r"(a[1]), "r"(a[2]), "r"(a[3]), "r"(b[0]), "r"(b[1]));
}

__device__ __forceinline__ void split2(float v, __nv_bfloat16& h, __nv_bfloat16& l) {
    h = __float2bfloat16(v);
    l = __float2bfloat16(v - __bfloat162float(h));
}

// ---------------------------------------------------------------------------
// Block reduce (256 threads = 8 warps)
// ---------------------------------------------------------------------------
__device__ __forceinline__ float blockReduceSum(float v, float* sbuf) {
    int lane = threadIdx.x & 31, wid = threadIdx.x >> 5;
    #pragma unroll
    for (int o = 16; o; o >>= 1) v += __shfl_xor_sync(0xffffffffu, v, o);
    if (lane == 0) sbuf[wid] = v;
    __syncthreads();
    if (wid == 0) {
        float w = (lane < 8) ? sbuf[lane] : 0.0f;
        #pragma unroll
        for (int o = 4; o; o >>= 1) w += __shfl_xor_sync(0xffffffffu, w, o);
        if (lane == 0) sbuf[0] = w;
    }
    __syncthreads();
    float r = sbuf[0];
    __syncthreads();
    return r;
}

// ---------------------------------------------------------------------------
// LayerNorm (torch-style) + optional bf16 hi/lo split outputs
// ---------------------------------------------------------------------------
__global__ void ln_kernel(const float* __restrict__ X,
                          const float* __restrict__ alpha,
                          const float* __restrict__ beta,
                          float* __restrict__ Y,
                          __nv_bfloat16* __restrict__ Yh,
                          __nv_bfloat16* __restrict__ Yl) {
    __shared__ float sbuf[8];
    size_t row = blockIdx.x;
    const float4* x4 = (const float4*)(X + row * D_);
    float4 xv = x4[threadIdx.x];
    float s = blockReduceSum(xv.x + xv.y + xv.z + xv.w, sbuf);
    float mu = s * (1.0f / D_);
    float d0 = xv.x - mu, d1 = xv.y - mu, d2 = xv.z - mu, d3 = xv.w - mu;
    float ssq = blockReduceSum(d0*d0 + d1*d1 + d2*d2 + d3*d3, sbuf);
    float inv = 1.0f / (sqrtf(ssq * (1.0f / (D_ - 1))) + 1e-6f);
    float4 a = ((const float4*)alpha)[threadIdx.x];
    float4 b = ((const float4*)beta)[threadIdx.x];
    float4 o;
    o.x = a.x * d0 * inv + b.x;
    o.y = a.y * d1 * inv + b.y;
    o.z = a.z * d2 * inv + b.z;
    o.w = a.w * d3 * inv + b.w;
    ((float4*)(Y + row * D_))[threadIdx.x] = o;
    if (Yh) {
        __nv_bfloat16 h0,l0,h1,l1,h2,l2,h3,l3;
        split2(o.x, h0, l0); split2(o.y, h1, l1);
        split2(o.z, h2, l2); split2(o.w, h3, l3);
        size_t off = row * D_ + threadIdx.x * 4;
        __nv_bfloat162* ph = (__nv_bfloat162*)(Yh + off);
        __nv_bfloat162* pl = (__nv_bfloat162*)(Yl + off);
        ph[0] = __nv_bfloat162(h0, h1); ph[1] = __nv_bfloat162(h2, h3);
        pl[0] = __nv_bfloat162(l0, l1); pl[1] = __nv_bfloat162(l2, l3);
    }
}

// ---------------------------------------------------------------------------
// Elementwise split: X (rows x ncols, contiguous) -> H/L with row stride ldout
// ---------------------------------------------------------------------------
__global__ void split_kernel(const float* __restrict__ X,
                             __nv_bfloat16* __restrict__ H,
                             __nv_bfloat16* __restrict__ L,
                             int ncols, int ldout, size_t total) {
    size_t i = (size_t)blockIdx.x * blockDim.x + threadIdx.x;
    if (i >= total) return;
    size_t r = i / ncols;
    int c = (int)(i - r * ncols);
    float v = X[i];
    __nv_bfloat16 h, l;
    split2(v, h, l);
    H[r * ldout + c] = h;
    L[r * ldout + c] = l;
}

// ---------------------------------------------------------------------------
// Transpose + split: W [K x N] row-major -> Th/Tl [N x K]
// ---------------------------------------------------------------------------
__global__ void tsplit_kernel(const float* __restrict__ W,
                              __nv_bfloat16* __restrict__ Th,
                              __nv_bfloat16* __restrict__ Tl,
                              int K, int N) {
    __shared__ float s[32][33];
    int nt = blockIdx.x * 32, kt = blockIdx.y * 32;
    int tx = threadIdx.x, ty = threadIdx.y;
    #pragma unroll
    for (int i = 0; i < 4; i++)
        s[ty + i * 8][tx] = W[(size_t)(kt + ty + i * 8) * N + nt + tx];
    __syncthreads();
    #pragma unroll
    for (int i = 0; i < 4; i++) {
        int n = nt + ty + i * 8;
        int k = kt + tx;
        float v = s[tx][ty + i * 8];
        __nv_bfloat16 h, l;
        split2(v, h, l);
        Th[(size_t)n * K + k] = h;
        Tl[(size_t)n * K + k] = l;
    }
}

// ---------------------------------------------------------------------------
// mma.sync bf16x3 GEMM: C[MxN] = (Ah+Al)[MxK, K-major] @ ((Bh+Bl)[NxK, K-major])^T
// CTA tile 128x128, K chunk 64. 8 warps, warp tile 64(M)x32(N).
// smem: SW128 swizzle (rows of 128B = 64 bf16), conflict-free ldmatrix.
// Epilogue fused: +bias, +resid, relu, fp32 C, optional bf16 hi/lo split out.
// ---------------------------------------------------------------------------
#define F_RELU  1
#define F_RESID 2

#define GEMM_SMEM (4 * 16384)

__global__ void __launch_bounds__(256)
gemm_mma(const __nv_bfloat16* __restrict__ Ah, const __nv_bfloat16* __restrict__ Al,
         const __nv_bfloat16* __restrict__ Bh, const __nv_bfloat16* __restrict__ Bl,
         const float* __restrict__ bias, const float* __restrict__ R,
         float* __restrict__ C,
         __nv_bfloat16* __restrict__ Ch, __nv_bfloat16* __restrict__ Cl,
         int M, int N, int K, int ld_split, int flags) {
    extern __shared__ char smem[];
    const uint32_t sbase = smem_to_u32(smem);
    const int tid = threadIdx.x;
    const int wid = tid >> 5, lane = tid & 31;
    const int rowBase = blockIdx.y * 128, colBase = blockIdx.x * 128;
    const int mWarp = wid & 1;        // 2 warps over M
    const int nWarp = wid >> 1;       // 4 warps over N

    float acc[4][4][4];
    #pragma unroll
    for (int i = 0; i < 4; i++)
        #pragma unroll
        for (int j = 0; j < 4; j++)
            #pragma unroll
            for (int t = 0; t < 4; t++) acc[i][j][t] = 0.f;

    // global->smem: thread covers row r (2 threads/row), 4x 16B chunks
    const int r  = tid >> 1;
    const int hf = tid & 1;

    for (int kt = 0; kt < K; kt += 64) {
        const uint4* gAh = (const uint4*)(Ah + (size_t)(rowBase + r) * K + kt);
        const uint4* gAl = (const uint4*)(Al + (size_t)(rowBase + r) * K + kt);
        const uint4* gBh = (const uint4*)(Bh + (size_t)(colBase + r) * K + kt);
        const uint4* gBl = (const uint4*)(Bl + (size_t)(colBase + r) * K + kt);
        #pragma unroll
        for (int i = 0; i < 4; i++) {
            int c16 = hf * 4 + i;
            uint32_t bo = (uint32_t)(r * 128) | (uint32_t)((c16 * 16) ^ ((r & 7) << 4));
            *(uint4*)(smem + bo)         = gAh[c16];
            *(uint4*)(smem + 16384 + bo) = gAl[c16];
            *(uint4*)(smem + 32768 + bo) = gBh[c16];
            *(uint4*)(smem + 49152 + bo) = gBl[c16];
        }
        __syncthreads();

        #pragma unroll
        for (int kk = 0; kk < 64; kk += 16) {
            uint32_t Ahf[4][4], Alf[4][4], Bhf[4][2], Blf[4][2];
            #pragma unroll
            for (int mi = 0; mi < 4; mi++) {
                int row = mWarp * 64 + mi * 16 + (lane & 15);
                uint32_t ko = (uint32_t)(kk * 2 + ((lane >> 4) << 4));
                uint32_t off = (uint32_t)(row * 128) | (ko ^ ((row & 7) << 4));
                ldsm_x4(Ahf[mi], sbase + off);
                ldsm_x4(Alf[mi], sbase + 16384 + off);
            }
            #pragma unroll
            for (int ni = 0; ni < 4; ni++) {
                int nrow = nWarp * 32 + ni * 8 + (lane & 7);
                uint32_t ko = (uint32_t)(kk * 2 + (((lane >> 3) & 1) << 4));
                uint32_t off = (uint32_t)(nrow * 128) | (ko ^ ((nrow & 7) << 4));
                ldsm_x2(Bhf[ni], sbase + 32768 + off);
                ldsm_x2(Blf[ni], sbase + 49152 + off);
            }
            #pragma unroll
            for (int mi = 0; mi < 4; mi++)
                #pragma unroll
                for (int ni = 0; ni < 4; ni++) {
                    mma_bf16(acc[mi][ni], Ahf[mi], Bhf[ni]);
                    mma_bf16(acc[mi][ni], Ahf[mi], Blf[ni]);
                    mma_bf16(acc[mi][ni], Alf[mi], Bhf[ni]);
                }
        }
        __syncthreads();
    }

    // epilogue: fragment (lane>>2, (lane&3)*2) rows +0/+8
    const int fr = lane >> 2;
    const int fc = (lane & 3) * 2;
    #pragma unroll
    for (int mi = 0; mi < 4; mi++) {
        int m0 = rowBase + mWarp * 64 + mi * 16;
        #pragma unroll
        for (int ni = 0; ni < 4; ni++) {
            int n0 = colBase + nWarp * 32 + ni * 8;
            int col = n0 + fc;
            float2 bv = make_float2(0.f, 0.f);
            if (bias) bv = *(const float2*)(bias + col);
            #pragma unroll
            for (int half = 0; half < 2; half++) {
                int row = m0 + fr + half * 8;
                float2 res;
                res.x = acc[mi][ni][half * 2 + 0] + bv.x;
                res.y = acc[mi][ni][half * 2 + 1] + bv.y;
                size_t off = (size_t)row * N + col;
                if (flags & F_RESID) {
                    float2 rv = *(const float2*)(R + off);
                    res.x += rv.x; res.y += rv.y;
                }
                if (flags & F_RELU) {
                    res.x = fmaxf(res.x, 0.f);
                    res.y = fmaxf(res.y, 0.f);
                }
                *(float2*)(C + off) = res;
                if (Ch) {
                    __nv_bfloat16 h0, l0, h1, l1;
                    split2(res.x, h0, l0);
                    split2(res.y, h1, l1);
                    size_t so = (size_t)row * ld_split + col;
                    *(__nv_bfloat162*)(Ch + so) = __nv_bfloat162(h0, h1);
                    *(__nv_bfloat162*)(Cl + so) = __nv_bfloat162(l0, l1);
                }
            }
        }
    }
}

// ---------------------------------------------------------------------------
// Flash attention fp32 (unchanged — next round's target)
// ---------------------------------------------------------------------------
__global__ void flash_kernel(const float* __restrict__ Q,
                             const float* __restrict__ K,
                             const float* __restrict__ V,
                             float* __restrict__ O) {
    __shared__ float Qt[64][64];
    __shared__ float KtPs[64][64];
    __shared__ float Vs[64][64];

    int tid = threadIdx.x;
    int tx = tid & 15, ty = tid >> 4;
    int b = blockIdx.y >> 4, h = blockIdx.y & 15;
    int qbase = blockIdx.x * 64;
    const size_t base = ((size_t)b * S_) * D_ + (size_t)h * DH;

    #pragma unroll
    for (int r = 0; r < 4; r++) {
        int qr = r * 16 + ty;
        float4 v = *(const float4*)(Q + base + (size_t)(qbase + qr) * D_ + tx * 4);
        Qt[tx * 4 + 0][qr] = v.x;
        Qt[tx * 4 + 1][qr] = v.y;
        Qt[tx * 4 + 2][qr] = v.z;
        Qt[tx * 4 + 3][qr] = v.w;
    }

    float m[4], l[4], o[4][4];
    #pragma unroll
    for (int i = 0; i < 4; i++) {
        m[i] = -1e30f; l[i] = 0.f;
        #pragma unroll
        for (int j = 0; j < 4; j++) o[i][j] = 0.f;
    }

    for (int kt = 0; kt < S_; kt += 64) {
        __syncthreads();
        #pragma unroll
        for (int r = 0; r < 4; r++) {
            int kr = r * 16 + ty;
            float4 kv = *(const float4*)(K + base + (size_t)(kt + kr) * D_ + tx * 4);
            KtPs[tx * 4 + 0][kr] = kv.x;
            KtPs[tx * 4 + 1][kr] = kv.y;
            KtPs[tx * 4 + 2][kr] = kv.z;
            KtPs[tx * 4 + 3][kr] = kv.w;
            float4 vv = *(const float4*)(V + base + (size_t)(kt + kr) * D_ + tx * 4);
            *(float4*)&Vs[kr][tx * 4] = vv;
        }
        __syncthreads();

        float s[4][4] = {};
        #pragma unroll
        for (int d = 0; d < 64; d++) {
            float4 a = *(const float4*)&Qt[d][ty * 4];
            float4 bb = *(const float4*)&KtPs[d][tx * 4];
            s[0][0] += a.x * bb.x; s[0][1] += a.x * bb.y; s[0][2] += a.x * bb.z; s[0][3] += a.x * bb.w;
            s[1][0] += a.y * bb.x; s[1][1] += a.y * bb.y; s[1][2] += a.y * bb.z; s[1][3] += a.y * bb.w;
            s[2][0] += a.z * bb.x; s[2][1] += a.z * bb.y; s[2][2] += a.z * bb.z; s[2][3] += a.z * bb.w;
            s[3][0] += a.w * bb.x; s[3][1] += a.w * bb.y; s[3][2] += a.w * bb.z; s[3][3] += a.w * bb.w;
        }

        float p[4][4];
        #pragma unroll
        for (int i = 0; i < 4; i++) {
            float tm = -1e30f;
            #pragma unroll
            for (int j = 0; j < 4; j++) { s[i][j] *= 0.125f; tm = fmaxf(tm, s[i][j]); }
            #pragma unroll
            for (int off = 1; off < 16; off <<= 1)
                tm = fmaxf(tm, __shfl_xor_sync(0xffffffffu, tm, off));
            float mn = fmaxf(m[i], tm);
            float sc = __expf(m[i] - mn);
            float rs = 0.f;
            #pragma unroll
            for (int j = 0; j < 4; j++) { p[i][j] = __expf(s[i][j] - mn); rs += p[i][j]; }
            #pragma unroll
            for (int off = 1; off < 16; off <<= 1)
                rs += __shfl_xor_sync(0xffffffffu, rs, off);
            l[i] = l[i] * sc + rs;
            m[i] = mn;
            #pragma unroll
            for (int j = 0; j < 4; j++) o[i][j] *= sc;
        }

        __syncthreads();
        #pragma unroll
        for (int i = 0; i < 4; i++)
            #pragma unroll
            for (int j = 0; j < 4; j++)
                KtPs[tx * 4 + j][ty * 4 + i] = p[i][j];
        __syncthreads();

        const float4* Ps4 = (const float4*)KtPs;
        const float4* Vs4 = (const float4*)Vs;
        #pragma unroll
        for (int k = 0; k < 64; k++) {
            float4 pv = Ps4[k * 16 + ty];
            float4 vv = Vs4[k * 16 + tx];
            o[0][0] += pv.x * vv.x; o[0][1] += pv.x * vv.y; o[0][2] += pv.x * vv.z; o[0][3] += pv.x * vv.w;
            o[1][0] += pv.y * vv.x; o[1][1] += pv.y * vv.y; o[1][2] += pv.y * vv.z; o[1][3] += pv.y * vv.w;
            o[2][0] += pv.z * vv.x; o[2][1] += pv.z * vv.y; o[2][2] += pv.z * vv.z; o[2][3] += pv.z * vv.w;
            o[3][0] += pv.w * vv.x; o[3][1] += pv.w * vv.y; o[3][2] += pv.w * vv.z; o[3][3] += pv.w * vv.w;
        }
    }

    #pragma unroll
    for (int i = 0; i < 4; i++) {
        float inv = 1.0f / l[i];
        float4 ov;
        ov.x = o[i][0] * inv; ov.y = o[i][1] * inv;
        ov.z = o[i][2] * inv; ov.w = o[i][3] * inv;
        *(float4*)(O + base + (size_t)(qbase + ty * 4 + i) * D_ + tx * 4) = ov;
    }
}

// ---------------------------------------------------------------------------
// Launch
// ---------------------------------------------------------------------------
extern "C" void kernel_launch(void* const* d_in, const int* in_sizes, int n_in,
                              void* d_out, int out_size) {
    const float* fx  = (const float*)d_in[0];
    const float* px  = (const float*)d_in[1];
    const float* Wq  = (const float*)d_in[2];
    const float* bq  = (const float*)d_in[3];
    const float* Wk  = (const float*)d_in[4];
    const float* bk  = (const float*)d_in[5];
    const float* Wv  = (const float*)d_in[6];
    const float* bv  = (const float*)d_in[7];
    const float* Wo  = (const float*)d_in[8];
    const float* bo  = (const float*)d_in[9];
    const float* a1  = (const float*)d_in[10];
    const float* be1 = (const float*)d_in[11];
    const float* a2  = (const float*)d_in[12];
    const float* be2 = (const float*)d_in[13];
    const float* W1  = (const float*)d_in[14];
    const float* b1  = (const float*)d_in[15];
    const float* W2  = (const float*)d_in[16];
    const float* b2  = (const float*)d_in[17];
    const float* Wp  = (const float*)d_in[18];
    const float* bp  = (const float*)d_in[19];

    float* scratch = nullptr;
    cudaGetSymbolAddress((void**)&scratch, g_scratch);
    __nv_bfloat16* bf = nullptr;
    cudaGetSymbolAddress((void**)&bf, g_bf16);

    float* xn  = scratch;
    float* q   = xn  + NM;
    float* k   = q   + NM;
    float* v   = k   + NM;
    float* ctx = v   + NM;
    float* x1  = ctx + NM;
    float* x2  = x1  + NM;
    float* hh  = x2  + NM;

    __nv_bfloat16 *xnh = bf + OFF_XNH,  *xnl = bf + OFF_XNL;
    __nv_bfloat16 *x2h = bf + OFF_X2H,  *x2l = bf + OFF_X2L;
    __nv_bfloat16 *ctxh= bf + OFF_CTXH, *ctxl= bf + OFF_CTXL;
    __nv_bfloat16 *hhh = bf + OFF_HHH,  *hhl = bf + OFF_HHL;
    __nv_bfloat16 *cath= bf + OFF_CATH, *catl= bf + OFF_CATL;
    __nv_bfloat16 *wqh = bf + OFF_WQH,  *wql = bf + OFF_WQL;
    __nv_bfloat16 *wkh = bf + OFF_WKH,  *wkl = bf + OFF_WKL;
    __nv_bfloat16 *wvh = bf + OFF_WVH,  *wvl = bf + OFF_WVL;
    __nv_bfloat16 *woh = bf + OFF_WOH,  *wol = bf + OFF_WOL;
    __nv_bfloat16 *w1h = bf + OFF_W1H,  *w1l = bf + OFF_W1L;
    __nv_bfloat16 *w2h = bf + OFF_W2H,  *w2l = bf + OFF_W2L;
    __nv_bfloat16 *wph = bf + OFF_WPH,  *wpl = bf + OFF_WPL;

    float* xo = (float*)d_out;
    float* pp = xo + NM;

    cudaFuncSetAttribute(gemm_mma, cudaFuncAttributeMaxDynamicSharedMemorySize, GEMM_SMEM);

    dim3 tb(32, 8);
    // Weight transpose+split: W [KxN] -> [NxK] hi/lo
    tsplit_kernel<<<dim3(D_/32, D_/32), tb>>>(Wq, wqh, wql, D_, D_);
    tsplit_kernel<<<dim3(D_/32, D_/32), tb>>>(Wk, wkh, wkl, D_, D_);
    tsplit_kernel<<<dim3(D_/32, D_/32), tb>>>(Wv, wvh, wvl, D_, D_);
    tsplit_kernel<<<dim3(D_/32, D_/32), tb>>>(Wo, woh, wol, D_, D_);
    tsplit_kernel<<<dim3(DFF_/32, D_/32), tb>>>(W1, w1h, w1l, D_, DFF_);
    tsplit_kernel<<<dim3(D_/32, DFF_/32), tb>>>(W2, w2h, w2l, DFF_, D_);
    tsplit_kernel<<<dim3(P_/32, CATW/32), tb>>>(Wp, wph, wpl, CATW, P_);

    // param_x split into cat buffer columns [D_, D_+P_)
    {
        size_t tot = (size_t)MROWS * P_;
        split_kernel<<<(unsigned)((tot + 255) / 256), 256>>>(
            px, cath + D_, catl + D_, P_, CATW, tot);
    }

    // 1. xn = LN1(fx), + hi/lo
    ln_kernel<<<MROWS, 256>>>(fx, a1, be1, xn, xnh, xnl);

    // 2-4. q/k/v = xn @ W{q,k,v} + b  (tensor cores)
    gemm_mma<<<dim3(D_/128, MROWS/128), 256, GEMM_SMEM>>>(
        xnh, xnl, wqh, wql, bq, nullptr, q, nullptr, nullptr, MROWS, D_, D_, 0, 0);
    gemm_mma<<<dim3(D_/128, MROWS/128), 256, GEMM_SMEM>>>(
        xnh, xnl, wkh, wkl, bk, nullptr, k, nullptr, nullptr, MROWS, D_, D_, 0, 0);
    gemm_mma<<<dim3(D_/128, MROWS/128), 256, GEMM_SMEM>>>(
        xnh, xnl, wvh, wvl, bv, nullptr, v, nullptr, nullptr, MROWS, D_, D_, 0, 0);

    // 5. attention (fp32 flash)
    flash_kernel<<<dim3(S_/64, B_*H_), 256>>>(q, k, v, ctx);

    // split ctx for Wo GEMM
    split_kernel<<<(unsigned)((NM + 255) / 256), 256>>>(ctx, ctxh, ctxl, D_, D_, NM);

    // 6. x1 = xn + ctx @ Wo + bo
    gemm_mma<<<dim3(D_/128, MROWS/128), 256, GEMM_SMEM>>>(
        ctxh, ctxl, woh, wol, bo, xn, x1, nullptr, nullptr, MROWS, D_, D_, 0, F_RESID);

    // 7. x2 = LN2(x1), + hi/lo
    ln_kernel<<<MROWS, 256>>>(x1, a2, be2, x2, x2h, x2l);

    // 8. hh = relu(x2 @ W1 + b1), + hi/lo
    gemm_mma<<<dim3(DFF_/128, MROWS/128), 256, GEMM_SMEM>>>(
        x2h, x2l, w1h, w1l, b1, nullptr, hh, hhh, hhl, MROWS, DFF_, D_, DFF_, F_RELU);

    // 9. x = x1 + hh @ W2 + b2 -> d_out, + split into cat[:, 0:D]
    gemm_mma<<<dim3(D_/128, MROWS/128), 256, GEMM_SMEM>>>(
        hhh, hhl, w2h, w2l, b2, x1, xo, cath, catl, MROWS, D_, DFF_, CATW, F_RESID);

    // 10. p = [x | px] @ Wp + bp   (single K=1280 GEMM)
    gemm_mma<<<dim3(P_/128, MROWS/128), 256, GEMM_SMEM>>>(
        cath, catl, wph, wpl, bp, nullptr, pp, nullptr, nullptr, MROWS, P_, CATW, 0, 0);
}

// round 4
// speedup vs baseline: 2.4268x; 1.8024x over previous
#include <cuda_runtime.h>
#include <cuda_bf16.h>
#include <math.h>
#include <stdint.h>

#define B_    4
#define S_    2048
#define D_    1024
#define H_    16
#define DH    64
#define DFF_  512
#define P_    256
#define MROWS (B_*S_)          // 8192
#define CATW  (D_ + P_)        // 1280

#define NM  ((size_t)MROWS * D_)      // 8388608
#define NH  ((size_t)MROWS * DFF_)    // 4194304
#define NC  ((size_t)MROWS * CATW)    // 10485760

// fp32 scratch: xn, x1, x2 (NM each) + hh (NH)
__device__ float g_scratch[3 * NM + NH];

// bf16 scratch (hi/lo pairs)
#define OFF_XNH   ((size_t)0)
#define OFF_XNL   (OFF_XNH + NM)
#define OFF_X2H   (OFF_XNL + NM)
#define OFF_X2L   (OFF_X2H + NM)
#define OFF_CTXH  (OFF_X2L + NM)
#define OFF_CTXL  (OFF_CTXH + NM)
#define OFF_QH    (OFF_CTXL + NM)
#define OFF_QL    (OFF_QH + NM)
#define OFF_KH    (OFF_QL + NM)
#define OFF_KL    (OFF_KH + NM)
#define OFF_VH    (OFF_KL + NM)
#define OFF_VL    (OFF_VH + NM)
#define OFF_HHH   (OFF_VL + NM)
#define OFF_HHL   (OFF_HHH + NH)
#define OFF_CATH  (OFF_HHL + NH)
#define OFF_CATL  (OFF_CATH + NC)
#define OFF_WQH   (OFF_CATL + NC)
#define OFF_WQL   (OFF_WQH + (size_t)D_*D_)
#define OFF_WKH   (OFF_WQL + (size_t)D_*D_)
#define OFF_WKL   (OFF_WKH + (size_t)D_*D_)
#define OFF_WVH   (OFF_WKL + (size_t)D_*D_)
#define OFF_WVL   (OFF_WVH + (size_t)D_*D_)
#define OFF_WOH   (OFF_WVL + (size_t)D_*D_)
#define OFF_WOL   (OFF_WOH + (size_t)D_*D_)
#define OFF_W1H   (OFF_WOL + (size_t)D_*D_)
#define OFF_W1L   (OFF_W1H + (size_t)D_*DFF_)
#define OFF_W2H   (OFF_W1L + (size_t)D_*DFF_)
#define OFF_W2L   (OFF_W2H + (size_t)D_*DFF_)
#define OFF_WPH   (OFF_W2L + (size_t)D_*DFF_)
#define OFF_WPL   (OFF_WPH + (size_t)CATW*P_)
#define BF_TOTAL  (OFF_WPL + (size_t)CATW*P_)

__device__ __nv_bfloat16 g_bf16[BF_TOTAL];

// ---------------------------------------------------------------------------
// family-safe tensor-core primitives (sm_80+; legal on plain sm_103 target)
// ---------------------------------------------------------------------------
__device__ __forceinline__ uint32_t smem_to_u32(const void* p) {
    uint32_t a;
    asm("{ .reg .u64 t; cvta.to.shared.u64 t, %1; cvt.u32.u64 %0, t; }" : "=r"(a) : "l"(p));
    return a;
}
__device__ __forceinline__ void ldsm_x4(uint32_t* r, uint32_t addr) {
    asm volatile("ldmatrix.sync.aligned.m8n8.x4.shared.b16 {%0,%1,%2,%3}, [%4];"
                 : "=r"(r[0]), "=r"(r[1]), "=r"(r[2]), "=r"(r[3]) : "r"(addr));
}
__device__ __forceinline__ void ldsm_x2(uint32_t* r, uint32_t addr) {
    asm volatile("ldmatrix.sync.aligned.m8n8.x2.shared.b16 {%0,%1}, [%2];"
                 : "=r"(r[0]), "=r"(r[1]) : "r"(addr));
}
__device__ __forceinline__ void ldsm_x2_trans(uint32_t* r, uint32_t addr) {
    asm volatile("ldmatrix.sync.aligned.m8n8.x2.trans.shared.b16 {%0,%1}, [%2];"
                 : "=r"(r[0]), "=r"(r[1]) : "r"(addr));
}
__device__ __forceinline__ void mma_bf16(float* c, const uint32_t* a, const uint32_t* b) {
    asm volatile(
        "mma.sync.aligned.m16n8k16.row.col.f32.bf16.bf16.f32 "
        "{%0,%1,%2,%3}, {%4,%5,%6,%7}, {%8,%9}, {%0,%1,%2,%3};"
        : "+f"(c[0]), "+f"(c[1]), "+f"(c[2]), "+f"(c[3])
        : "r"(a[0]), "r"(a[1]), "r"(a[2]), "r"(a[3]), "r"(b[0]), "r"(b[1]));
}

__device__ __forceinline__ void split2(float v, __nv_bfloat16& h, __nv_bfloat16& l) {
    h = __float2bfloat16(v);
    l = __float2bfloat16(v - __bfloat162float(h));
}
__device__ __forceinline__ uint32_t pack_bf2(float a, float b) {
    __nv_bfloat162 t(__float2bfloat16(a), __float2bfloat16(b));
    return *(uint32_t*)&t;
}

// ---------------------------------------------------------------------------
// Block reduce (256 threads = 8 warps)
// ---------------------------------------------------------------------------
__device__ __forceinline__ float blockReduceSum(float v, float* sbuf) {
    int lane = threadIdx.x & 31, wid = threadIdx.x >> 5;
    #pragma unroll
    for (int o = 16; o; o >>= 1) v += __shfl_xor_sync(0xffffffffu, v, o);
    if (lane == 0) sbuf[wid] = v;
    __syncthreads();
    if (wid == 0) {
        float w = (lane < 8) ? sbuf[lane] : 0.0f;
        #pragma unroll
        for (int o = 4; o; o >>= 1) w += __shfl_xor_sync(0xffffffffu, w, o);
        if (lane == 0) sbuf[0] = w;
    }
    __syncthreads();
    float r = sbuf[0];
    __syncthreads();
    return r;
}

// ---------------------------------------------------------------------------
// LayerNorm (torch-style) + optional bf16 hi/lo split outputs
// ---------------------------------------------------------------------------
__global__ void ln_kernel(const float* __restrict__ X,
                          const float* __restrict__ alpha,
                          const float* __restrict__ beta,
                          float* __restrict__ Y,
                          __nv_bfloat16* __restrict__ Yh,
                          __nv_bfloat16* __restrict__ Yl) {
    __shared__ float sbuf[8];
    size_t row = blockIdx.x;
    const float4* x4 = (const float4*)(X + row * D_);
    float4 xv = x4[threadIdx.x];
    float s = blockReduceSum(xv.x + xv.y + xv.z + xv.w, sbuf);
    float mu = s * (1.0f / D_);
    float d0 = xv.x - mu, d1 = xv.y - mu, d2 = xv.z - mu, d3 = xv.w - mu;
    float ssq = blockReduceSum(d0*d0 + d1*d1 + d2*d2 + d3*d3, sbuf);
    float inv = 1.0f / (sqrtf(ssq * (1.0f / (D_ - 1))) + 1e-6f);
    float4 a = ((const float4*)alpha)[threadIdx.x];
    float4 b = ((const float4*)beta)[threadIdx.x];
    float4 o;
    o.x = a.x * d0 * inv + b.x;
    o.y = a.y * d1 * inv + b.y;
    o.z = a.z * d2 * inv + b.z;
    o.w = a.w * d3 * inv + b.w;
    ((float4*)(Y + row * D_))[threadIdx.x] = o;
    if (Yh) {
        __nv_bfloat16 h0,l0,h1,l1,h2,l2,h3,l3;
        split2(o.x, h0, l0); split2(o.y, h1, l1);
        split2(o.z, h2, l2); split2(o.w, h3, l3);
        size_t off = row * D_ + threadIdx.x * 4;
        __nv_bfloat162* ph = (__nv_bfloat162*)(Yh + off);
        __nv_bfloat162* pl = (__nv_bfloat162*)(Yl + off);
        ph[0] = __nv_bfloat162(h0, h1); ph[1] = __nv_bfloat162(h2, h3);
        pl[0] = __nv_bfloat162(l0, l1); pl[1] = __nv_bfloat162(l2, l3);
    }
}

// ---------------------------------------------------------------------------
// Elementwise split: X (rows x ncols, contiguous) -> H/L with row stride ldout
// ---------------------------------------------------------------------------
__global__ void split_kernel(const float* __restrict__ X,
                             __nv_bfloat16* __restrict__ H,
                             __nv_bfloat16* __restrict__ L,
                             int ncols, int ldout, size_t total) {
    size_t i = (size_t)blockIdx.x * blockDim.x + threadIdx.x;
    if (i >= total) return;
    size_t r = i / ncols;
    int c = (int)(i - r * ncols);
    float v = X[i];
    __nv_bfloat16 h, l;
    split2(v, h, l);
    H[r * ldout + c] = h;
    L[r * ldout + c] = l;
}

// ---------------------------------------------------------------------------
// Transpose + split: W [K x N] row-major -> Th/Tl [N x K]
// ---------------------------------------------------------------------------
__global__ void tsplit_kernel(const float* __restrict__ W,
                              __nv_bfloat16* __restrict__ Th,
                              __nv_bfloat16* __restrict__ Tl,
                              int K, int N) {
    __shared__ float s[32][33];
    int nt = blockIdx.x * 32, kt = blockIdx.y * 32;
    int tx = threadIdx.x, ty = threadIdx.y;
    #pragma unroll
    for (int i = 0; i < 4; i++)
        s[ty + i * 8][tx] = W[(size_t)(kt + ty + i * 8) * N + nt + tx];
    __syncthreads();
    #pragma unroll
    for (int i = 0; i < 4; i++) {
        int n = nt + ty + i * 8;
        int k = kt + tx;
        float v = s[tx][ty + i * 8];
        __nv_bfloat16 h, l;
        split2(v, h, l);
        Th[(size_t)n * K + k] = h;
        Tl[(size_t)n * K + k] = l;
    }
}

// ---------------------------------------------------------------------------
// mma.sync bf16x3 GEMM (as round 3, C now optional)
// ---------------------------------------------------------------------------
#define F_RELU  1
#define F_RESID 2

#define GEMM_SMEM (4 * 16384)

__global__ void __launch_bounds__(256)
gemm_mma(const __nv_bfloat16* __restrict__ Ah, const __nv_bfloat16* __restrict__ Al,
         const __nv_bfloat16* __restrict__ Bh, const __nv_bfloat16* __restrict__ Bl,
         const float* __restrict__ bias, const float* __restrict__ R,
         float* __restrict__ C,
         __nv_bfloat16* __restrict__ Ch, __nv_bfloat16* __restrict__ Cl,
         int M, int N, int K, int ld_split, int flags) {
    extern __shared__ char smem[];
    const uint32_t sbase = smem_to_u32(smem);
    const int tid = threadIdx.x;
    const int wid = tid >> 5, lane = tid & 31;
    const int rowBase = blockIdx.y * 128, colBase = blockIdx.x * 128;
    const int mWarp = wid & 1;
    const int nWarp = wid >> 1;

    float acc[4][4][4];
    #pragma unroll
    for (int i = 0; i < 4; i++)
        #pragma unroll
        for (int j = 0; j < 4; j++)
            #pragma unroll
            for (int t = 0; t < 4; t++) acc[i][j][t] = 0.f;

    const int r  = tid >> 1;
    const int hf = tid & 1;

    for (int kt = 0; kt < K; kt += 64) {
        const uint4* gAh = (const uint4*)(Ah + (size_t)(rowBase + r) * K + kt);
        const uint4* gAl = (const uint4*)(Al + (size_t)(rowBase + r) * K + kt);
        const uint4* gBh = (const uint4*)(Bh + (size_t)(colBase + r) * K + kt);
        const uint4* gBl = (const uint4*)(Bl + (size_t)(colBase + r) * K + kt);
        #pragma unroll
        for (int i = 0; i < 4; i++) {
            int c16 = hf * 4 + i;
            uint32_t bo = (uint32_t)(r * 128) | (uint32_t)((c16 * 16) ^ ((r & 7) << 4));
            *(uint4*)(smem + bo)         = gAh[c16];
            *(uint4*)(smem + 16384 + bo) = gAl[c16];
            *(uint4*)(smem + 32768 + bo) = gBh[c16];
            *(uint4*)(smem + 49152 + bo) = gBl[c16];
        }
        __syncthreads();

        #pragma unroll
        for (int kk = 0; kk < 64; kk += 16) {
            uint32_t Ahf[4][4], Alf[4][4], Bhf[4][2], Blf[4][2];
            #pragma unroll
            for (int mi = 0; mi < 4; mi++) {
                int row = mWarp * 64 + mi * 16 + (lane & 15);
                uint32_t ko = (uint32_t)(kk * 2 + ((lane >> 4) << 4));
                uint32_t off = (uint32_t)(row * 128) | (ko ^ ((row & 7) << 4));
                ldsm_x4(Ahf[mi], sbase + off);
                ldsm_x4(Alf[mi], sbase + 16384 + off);
            }
            #pragma unroll
            for (int ni = 0; ni < 4; ni++) {
                int nrow = nWarp * 32 + ni * 8 + (lane & 7);
                uint32_t ko = (uint32_t)(kk * 2 + (((lane >> 3) & 1) << 4));
                uint32_t off = (uint32_t)(nrow * 128) | (ko ^ ((nrow & 7) << 4));
                ldsm_x2(Bhf[ni], sbase + 32768 + off);
                ldsm_x2(Blf[ni], sbase + 49152 + off);
            }
            #pragma unroll
            for (int mi = 0; mi < 4; mi++)
                #pragma unroll
                for (int ni = 0; ni < 4; ni++) {
                    mma_bf16(acc[mi][ni], Ahf[mi], Bhf[ni]);
                    mma_bf16(acc[mi][ni], Ahf[mi], Blf[ni]);
                    mma_bf16(acc[mi][ni], Alf[mi], Bhf[ni]);
                }
        }
        __syncthreads();
    }

    const int fr = lane >> 2;
    const int fc = (lane & 3) * 2;
    #pragma unroll
    for (int mi = 0; mi < 4; mi++) {
        int m0 = rowBase + mWarp * 64 + mi * 16;
        #pragma unroll
        for (int ni = 0; ni < 4; ni++) {
            int n0 = colBase + nWarp * 32 + ni * 8;
            int col = n0 + fc;
            float2 bv = make_float2(0.f, 0.f);
            if (bias) bv = *(const float2*)(bias + col);
            #pragma unroll
            for (int half = 0; half < 2; half++) {
                int row = m0 + fr + half * 8;
                float2 res;
                res.x = acc[mi][ni][half * 2 + 0] + bv.x;
                res.y = acc[mi][ni][half * 2 + 1] + bv.y;
                size_t off = (size_t)row * N + col;
                if (flags & F_RESID) {
                    float2 rv = *(const float2*)(R + off);
                    res.x += rv.x; res.y += rv.y;
                }
                if (flags & F_RELU) {
                    res.x = fmaxf(res.x, 0.f);
                    res.y = fmaxf(res.y, 0.f);
                }
                if (C) *(float2*)(C + off) = res;
                if (Ch) {
                    __nv_bfloat16 h0, l0, h1, l1;
                    split2(res.x, h0, l0);
                    split2(res.y, h1, l1);
                    size_t so = (size_t)row * ld_split + col;
                    *(__nv_bfloat162*)(Ch + so) = __nv_bfloat162(h0, h1);
                    *(__nv_bfloat162*)(Cl + so) = __nv_bfloat162(l0, l1);
                }
            }
        }
    }
}

// ---------------------------------------------------------------------------
// Flash attention, bf16x3 mma.sync.
// grid (S_/128, B_*H_), 256 threads (8 warps x 16 q-rows).
// smem: Qh/Ql 128x64, Kh/Kl 64x64, Vh/Vl 64x64 (all 128B swizzled rows) = 64KB
// ---------------------------------------------------------------------------
#define FLASH_SMEM 65536

__global__ void __launch_bounds__(256)
flash_mma(const __nv_bfloat16* __restrict__ Qh, const __nv_bfloat16* __restrict__ Ql,
          const __nv_bfloat16* __restrict__ Kh, const __nv_bfloat16* __restrict__ Kl,
          const __nv_bfloat16* __restrict__ Vh, const __nv_bfloat16* __restrict__ Vl,
          __nv_bfloat16* __restrict__ Ch, __nv_bfloat16* __restrict__ Cl) {
    extern __shared__ char smem[];
    const uint32_t sbase = smem_to_u32(smem);
    const int tid = threadIdx.x;
    const int wid = tid >> 5, lane = tid & 31;
    const int b = blockIdx.y >> 4, h = blockIdx.y & 15;
    const int qbase = blockIdx.x * 128;
    const size_t rowBase = (size_t)b * S_;
    const int colOff = h * DH;

    const uint32_t oQh = 0, oQl = 16384, oKh = 32768, oKl = 40960, oVh = 49152, oVl = 57344;

    // load Q tile (128 rows x 64 cols) hi/lo
    {
        int r = tid >> 1, hf = tid & 1;
        const uint4* gqh = (const uint4*)(Qh + (rowBase + qbase + r) * D_ + colOff);
        const uint4* gql = (const uint4*)(Ql + (rowBase + qbase + r) * D_ + colOff);
        #pragma unroll
        for (int i = 0; i < 4; i++) {
            int c16 = hf * 4 + i;
            uint32_t bo = (uint32_t)(r * 128) | (uint32_t)((c16 * 16) ^ ((r & 7) << 4));
            *(uint4*)(smem + oQh + bo) = gqh[c16];
            *(uint4*)(smem + oQl + bo) = gql[c16];
        }
    }
    __syncthreads();

    // hoist Q fragments (per warp, all 4 k-steps)
    uint32_t QhA[4][4], QlA[4][4];
    #pragma unroll
    for (int ks = 0; ks < 4; ks++) {
        int row = wid * 16 + (lane & 15);
        uint32_t ko = (uint32_t)(ks * 32 + ((lane >> 4) << 4));
        uint32_t off = (uint32_t)(row * 128) | (ko ^ ((row & 7) << 4));
        ldsm_x4(QhA[ks], sbase + oQh + off);
        ldsm_x4(QlA[ks], sbase + oQl + off);
    }

    float m0 = -1e30f, m1 = -1e30f, l0 = 0.f, l1 = 0.f;
    float o[8][4];
    #pragma unroll
    for (int nt = 0; nt < 8; nt++)
        #pragma unroll
        for (int j = 0; j < 4; j++) o[nt][j] = 0.f;

    for (int kt = 0; kt < S_; kt += 64) {
        __syncthreads();   // prior K/V readers done
        {
            int r = tid >> 2, qd = tid & 3;
            const uint4* gkh = (const uint4*)(Kh + (rowBase + kt + r) * D_ + colOff);
            const uint4* gkl = (const uint4*)(Kl + (rowBase + kt + r) * D_ + colOff);
            const uint4* gvh = (const uint4*)(Vh + (rowBase + kt + r) * D_ + colOff);
            const uint4* gvl = (const uint4*)(Vl + (rowBase + kt + r) * D_ + colOff);
            #pragma unroll
            for (int i = 0; i < 2; i++) {
                int c16 = qd * 2 + i;
                uint32_t bo = (uint32_t)(r * 128) | (uint32_t)((c16 * 16) ^ ((r & 7) << 4));
                *(uint4*)(smem + oKh + bo) = gkh[c16];
                *(uint4*)(smem + oKl + bo) = gkl[c16];
                *(uint4*)(smem + oVh + bo) = gvh[c16];
                *(uint4*)(smem + oVl + bo) = gvl[c16];
            }
        }
        __syncthreads();

        // S = Q @ K^T  (bf16x3)
        float s[8][4];
        #pragma unroll
        for (int nt = 0; nt < 8; nt++)
            #pragma unroll
            for (int j = 0; j < 4; j++) s[nt][j] = 0.f;
        #pragma unroll
        for (int ks = 0; ks < 4; ks++) {
            #pragma unroll
            for (int nt = 0; nt < 8; nt++) {
                uint32_t Bh_[2], Bl_[2];
                int nrow = nt * 8 + (lane & 7);
                uint32_t ko = (uint32_t)(ks * 32 + (((lane >> 3) & 1) << 4));
                uint32_t off = (uint32_t)(nrow * 128) | (ko ^ ((nrow & 7) << 4));
                ldsm_x2(Bh_, sbase + oKh + off);
                ldsm_x2(Bl_, sbase + oKl + off);
                mma_bf16(s[nt], QhA[ks], Bh_);
                mma_bf16(s[nt], QhA[ks], Bl_);
                mma_bf16(s[nt], QlA[ks], Bh_);
            }
        }

        // online softmax on fragments (rows: r0=lane>>2 for c0/c1, r0+8 for c2/c3)
        float tm0 = -1e30f, tm1 = -1e30f;
        #pragma unroll
        for (int nt = 0; nt < 8; nt++) {
            #pragma unroll
            for (int j = 0; j < 4; j++) s[nt][j] *= 0.125f;
            tm0 = fmaxf(tm0, fmaxf(s[nt][0], s[nt][1]));
            tm1 = fmaxf(tm1, fmaxf(s[nt][2], s[nt][3]));
        }
        tm0 = fmaxf(tm0, __shfl_xor_sync(0xffffffffu, tm0, 1));
        tm0 = fmaxf(tm0, __shfl_xor_sync(0xffffffffu, tm0, 2));
        tm1 = fmaxf(tm1, __shfl_xor_sync(0xffffffffu, tm1, 1));
        tm1 = fmaxf(tm1, __shfl_xor_sync(0xffffffffu, tm1, 2));
        float mn0 = fmaxf(m0, tm0), mn1 = fmaxf(m1, tm1);
        float sc0 = __expf(m0 - mn0), sc1 = __expf(m1 - mn1);
        float rs0 = 0.f, rs1 = 0.f;
        #pragma unroll
        for (int nt = 0; nt < 8; nt++) {
            s[nt][0] = __expf(s[nt][0] - mn0);
            s[nt][1] = __expf(s[nt][1] - mn0);
            s[nt][2] = __expf(s[nt][2] - mn1);
            s[nt][3] = __expf(s[nt][3] - mn1);
            rs0 += s[nt][0] + s[nt][1];
            rs1 += s[nt][2] + s[nt][3];
        }
        rs0 += __shfl_xor_sync(0xffffffffu, rs0, 1);
        rs0 += __shfl_xor_sync(0xffffffffu, rs0, 2);
        rs1 += __shfl_xor_sync(0xffffffffu, rs1, 1);
        rs1 += __shfl_xor_sync(0xffffffffu, rs1, 2);
        l0 = l0 * sc0 + rs0;
        l1 = l1 * sc1 + rs1;
        m0 = mn0; m1 = mn1;
        #pragma unroll
        for (int nt = 0; nt < 8; nt++) {
            o[nt][0] *= sc0; o[nt][1] *= sc0;
            o[nt][2] *= sc1; o[nt][3] *= sc1;
        }

        // P fragments (C-layout -> A-layout), hi/lo split
        uint32_t PhA[4][4], PlA[4][4];
        #pragma unroll
        for (int ks = 0; ks < 4; ks++) {
            float* e = s[2 * ks];
            float* q = s[2 * ks + 1];
            __nv_bfloat16 h, l;
            float r0[4] = {e[0], e[1], e[2], e[3]};
            float r1[4] = {q[0], q[1], q[2], q[3]};
            __nv_bfloat16 hh0[4], ll0[4], hh1[4], ll1[4];
            #pragma unroll
            for (int j = 0; j < 4; j++) { split2(r0[j], h, l); hh0[j] = h; ll0[j] = l; }
            #pragma unroll
            for (int j = 0; j < 4; j++) { split2(r1[j], h, l); hh1[j] = h; ll1[j] = l; }
            __nv_bfloat162 t;
            t = __nv_bfloat162(hh0[0], hh0[1]); PhA[ks][0] = *(uint32_t*)&t;
            t = __nv_bfloat162(hh0[2], hh0[3]); PhA[ks][1] = *(uint32_t*)&t;
            t = __nv_bfloat162(hh1[0], hh1[1]); PhA[ks][2] = *(uint32_t*)&t;
            t = __nv_bfloat162(hh1[2], hh1[3]); PhA[ks][3] = *(uint32_t*)&t;
            t = __nv_bfloat162(ll0[0], ll0[1]); PlA[ks][0] = *(uint32_t*)&t;
            t = __nv_bfloat162(ll0[2], ll0[3]); PlA[ks][1] = *(uint32_t*)&t;
            t = __nv_bfloat162(ll1[0], ll1[1]); PlA[ks][2] = *(uint32_t*)&t;
            t = __nv_bfloat162(ll1[2], ll1[3]); PlA[ks][3] = *(uint32_t*)&t;
        }

        // O += P @ V  (V via ldmatrix.trans from natural [key][dh] layout)
        #pragma unroll
        for (int nt = 0; nt < 8; nt++) {
            #pragma unroll
            for (int ks = 0; ks < 4; ks++) {
                uint32_t Bh_[2], Bl_[2];
                int krow = ks * 16 + (lane & 15);
                uint32_t off = (uint32_t)(krow * 128) |
                               ((uint32_t)(nt * 16) ^ ((krow & 7) << 4));
                ldsm_x2_trans(Bh_, sbase + oVh + off);
                ldsm_x2_trans(Bl_, sbase + oVl + off);
                mma_bf16(o[nt], PhA[ks], Bh_);
                mma_bf16(o[nt], PhA[ks], Bl_);
                mma_bf16(o[nt], PlA[ks], Bh_);
            }
        }
    }

    // epilogue: normalize, split hi/lo, write ctx
    float inv0 = 1.0f / l0, inv1 = 1.0f / l1;
    int fr = lane >> 2, fc = (lane & 3) * 2;
    int r0 = qbase + wid * 16 + fr;
    #pragma unroll
    for (int nt = 0; nt < 8; nt++) {
        int col = colOff + nt * 8 + fc;
        float v0 = o[nt][0] * inv0, v1 = o[nt][1] * inv0;
        float v2 = o[nt][2] * inv1, v3 = o[nt][3] * inv1;
        __nv_bfloat16 h0,lo0,h1,lo1,h2,lo2,h3,lo3;
        split2(v0, h0, lo0); split2(v1, h1, lo1);
        split2(v2, h2, lo2); split2(v3, h3, lo3);
        size_t off0 = (rowBase + r0) * D_ + col;
        size_t off1 = (rowBase + r0 + 8) * D_ + col;
        *(__nv_bfloat162*)(Ch + off0) = __nv_bfloat162(h0, h1);
        *(__nv_bfloat162*)(Cl + off0) = __nv_bfloat162(lo0, lo1);
        *(__nv_bfloat162*)(Ch + off1) = __nv_bfloat162(h2, h3);
        *(__nv_bfloat162*)(Cl + off1) = __nv_bfloat162(lo2, lo3);
    }
}

// ---------------------------------------------------------------------------
// Launch
// ---------------------------------------------------------------------------
extern "C" void kernel_launch(void* const* d_in, const int* in_sizes, int n_in,
                              void* d_out, int out_size) {
    const float* fx  = (const float*)d_in[0];
    const float* px  = (const float*)d_in[1];
    const float* Wq  = (const float*)d_in[2];
    const float* bq  = (const float*)d_in[3];
    const float* Wk  = (const float*)d_in[4];
    const float* bk  = (const float*)d_in[5];
    const float* Wv  = (const float*)d_in[6];
    const float* bv  = (const float*)d_in[7];
    const float* Wo  = (const float*)d_in[8];
    const float* bo  = (const float*)d_in[9];
    const float* a1  = (const float*)d_in[10];
    const float* be1 = (const float*)d_in[11];
    const float* a2  = (const float*)d_in[12];
    const float* be2 = (const float*)d_in[13];
    const float* W1  = (const float*)d_in[14];
    const float* b1  = (const float*)d_in[15];
    const float* W2  = (const float*)d_in[16];
    const float* b2  = (const float*)d_in[17];
    const float* Wp  = (const float*)d_in[18];
    const float* bp  = (const float*)d_in[19];

    float* scratch = nullptr;
    cudaGetSymbolAddress((void**)&scratch, g_scratch);
    __nv_bfloat16* bf = nullptr;
    cudaGetSymbolAddress((void**)&bf, g_bf16);

    float* xn  = scratch;
    float* x1  = xn + NM;
    float* x2  = x1 + NM;
    float* hh  = x2 + NM;

    __nv_bfloat16 *xnh = bf + OFF_XNH,  *xnl = bf + OFF_XNL;
    __nv_bfloat16 *x2h = bf + OFF_X2H,  *x2l = bf + OFF_X2L;
    __nv_bfloat16 *ctxh= bf + OFF_CTXH, *ctxl= bf + OFF_CTXL;
    __nv_bfloat16 *qh  = bf + OFF_QH,   *ql  = bf + OFF_QL;
    __nv_bfloat16 *kh  = bf + OFF_KH,   *kl  = bf + OFF_KL;
    __nv_bfloat16 *vh  = bf + OFF_VH,   *vl  = bf + OFF_VL;
    __nv_bfloat16 *hhh = bf + OFF_HHH,  *hhl = bf + OFF_HHL;
    __nv_bfloat16 *cath= bf + OFF_CATH, *catl= bf + OFF_CATL;
    __nv_bfloat16 *wqh = bf + OFF_WQH,  *wql = bf + OFF_WQL;
    __nv_bfloat16 *wkh = bf + OFF_WKH,  *wkl = bf + OFF_WKL;
    __nv_bfloat16 *wvh = bf + OFF_WVH,  *wvl = bf + OFF_WVL;
    __nv_bfloat16 *woh = bf + OFF_WOH,  *wol = bf + OFF_WOL;
    __nv_bfloat16 *w1h = bf + OFF_W1H,  *w1l = bf + OFF_W1L;
    __nv_bfloat16 *w2h = bf + OFF_W2H,  *w2l = bf + OFF_W2L;
    __nv_bfloat16 *wph = bf + OFF_WPH,  *wpl = bf + OFF_WPL;

    float* xo = (float*)d_out;
    float* pp = xo + NM;

    cudaFuncSetAttribute(gemm_mma, cudaFuncAttributeMaxDynamicSharedMemorySize, GEMM_SMEM);
    cudaFuncSetAttribute(flash_mma, cudaFuncAttributeMaxDynamicSharedMemorySize, FLASH_SMEM);

    dim3 tb(32, 8);
    tsplit_kernel<<<dim3(D_/32, D_/32), tb>>>(Wq, wqh, wql, D_, D_);
    tsplit_kernel<<<dim3(D_/32, D_/32), tb>>>(Wk, wkh, wkl, D_, D_);
    tsplit_kernel<<<dim3(D_/32, D_/32), tb>>>(Wv, wvh, wvl, D_, D_);
    tsplit_kernel<<<dim3(D_/32, D_/32), tb>>>(Wo, woh, wol, D_, D_);
    tsplit_kernel<<<dim3(DFF_/32, D_/32), tb>>>(W1, w1h, w1l, D_, DFF_);
    tsplit_kernel<<<dim3(D_/32, DFF_/32), tb>>>(W2, w2h, w2l, DFF_, D_);
    tsplit_kernel<<<dim3(P_/32, CATW/32), tb>>>(Wp, wph, wpl, CATW, P_);

    // param_x split into cat buffer columns [D_, D_+P_)
    {
        size_t tot = (size_t)MROWS * P_;
        split_kernel<<<(unsigned)((tot + 255) / 256), 256>>>(
            px, cath + D_, catl + D_, P_, CATW, tot);
    }

    // 1. xn = LN1(fx), + hi/lo
    ln_kernel<<<MROWS, 256>>>(fx, a1, be1, xn, xnh, xnl);

    // 2-4. q/k/v (bf16 hi/lo outputs only — no fp32 store)
    gemm_mma<<<dim3(D_/128, MROWS/128), 256, GEMM_SMEM>>>(
        xnh, xnl, wqh, wql, bq, nullptr, nullptr, qh, ql, MROWS, D_, D_, D_, 0);
    gemm_mma<<<dim3(D_/128, MROWS/128), 256, GEMM_SMEM>>>(
        xnh, xnl, wkh, wkl, bk, nullptr, nullptr, kh, kl, MROWS, D_, D_, D_, 0);
    gemm_mma<<<dim3(D_/128, MROWS/128), 256, GEMM_SMEM>>>(
        xnh, xnl, wvh, wvl, bv, nullptr, nullptr, vh, vl, MROWS, D_, D_, D_, 0);

    // 5. attention (tensor-core flash) -> ctx hi/lo
    flash_mma<<<dim3(S_/128, B_*H_), 256, FLASH_SMEM>>>(qh, ql, kh, kl, vh, vl, ctxh, ctxl);

    // 6. x1 = xn + ctx @ Wo + bo
    gemm_mma<<<dim3(D_/128, MROWS/128), 256, GEMM_SMEM>>>(
        ctxh, ctxl, woh, wol, bo, xn, x1, nullptr, nullptr, MROWS, D_, D_, 0, F_RESID);

    // 7. x2 = LN2(x1), + hi/lo
    ln_kernel<<<MROWS, 256>>>(x1, a2, be2, x2, x2h, x2l);

    // 8. hh = relu(x2 @ W1 + b1), + hi/lo
    gemm_mma<<<dim3(DFF_/128, MROWS/128), 256, GEMM_SMEM>>>(
        x2h, x2l, w1h, w1l, b1, nullptr, hh, hhh, hhl, MROWS, DFF_, D_, DFF_, F_RELU);

    // 9. x = x1 + hh @ W2 + b2 -> d_out, + split into cat[:, 0:D]
    gemm_mma<<<dim3(D_/128, MROWS/128), 256, GEMM_SMEM>>>(
        hhh, hhl, w2h, w2l, b2, x1, xo, cath, catl, MROWS, D_, DFF_, CATW, F_RESID);

    // 10. p = [x | px] @ Wp + bp   (single K=1280 GEMM)
    gemm_mma<<<dim3(P_/128, MROWS/128), 256, GEMM_SMEM>>>(
        cath, catl, wph, wpl, bp, nullptr, pp, nullptr, nullptr, MROWS, P_, CATW, 0, 0);
}

// round 5
// speedup vs baseline: 3.0173x; 1.2433x over previous
#include <cuda_runtime.h>
#include <cuda_bf16.h>
#include <math.h>
#include <stdint.h>

#define B_    4
#define S_    2048
#define D_    1024
#define H_    16
#define DH    64
#define DFF_  512
#define P_    256
#define MROWS (B_*S_)          // 8192
#define CATW  (D_ + P_)        // 1280

#define NM  ((size_t)MROWS * D_)      // 8388608
#define NH  ((size_t)MROWS * DFF_)    // 4194304
#define NC  ((size_t)MROWS * CATW)    // 10485760

// fp32 scratch: xn, x1, x2 (NM each) + hh (NH)
__device__ float g_scratch[3 * NM + NH];

// bf16 scratch (hi/lo pairs)
#define OFF_XNH   ((size_t)0)
#define OFF_XNL   (OFF_XNH + NM)
#define OFF_X2H   (OFF_XNL + NM)
#define OFF_X2L   (OFF_X2H + NM)
#define OFF_CTXH  (OFF_X2L + NM)
#define OFF_CTXL  (OFF_CTXH + NM)
#define OFF_QH    (OFF_CTXL + NM)
#define OFF_QL    (OFF_QH + NM)
#define OFF_KH    (OFF_QL + NM)
#define OFF_KL    (OFF_KH + NM)
#define OFF_VH    (OFF_KL + NM)
#define OFF_VL    (OFF_VH + NM)
#define OFF_HHH   (OFF_VL + NM)
#define OFF_HHL   (OFF_HHH + NH)
#define OFF_CATH  (OFF_HHL + NH)
#define OFF_CATL  (OFF_CATH + NC)
#define OFF_WQH   (OFF_CATL + NC)
#define OFF_WQL   (OFF_WQH + (size_t)D_*D_)
#define OFF_WKH   (OFF_WQL + (size_t)D_*D_)
#define OFF_WKL   (OFF_WKH + (size_t)D_*D_)
#define OFF_WVH   (OFF_WKL + (size_t)D_*D_)
#define OFF_WVL   (OFF_WVH + (size_t)D_*D_)
#define OFF_WOH   (OFF_WVL + (size_t)D_*D_)
#define OFF_WOL   (OFF_WOH + (size_t)D_*D_)
#define OFF_W1H   (OFF_WOL + (size_t)D_*D_)
#define OFF_W1L   (OFF_W1H + (size_t)D_*DFF_)
#define OFF_W2H   (OFF_W1L + (size_t)D_*DFF_)
#define OFF_W2L   (OFF_W2H + (size_t)D_*DFF_)
#define OFF_WPH   (OFF_W2L + (size_t)D_*DFF_)
#define OFF_WPL   (OFF_WPH + (size_t)CATW*P_)
#define BF_TOTAL  (OFF_WPL + (size_t)CATW*P_)

__device__ __nv_bfloat16 g_bf16[BF_TOTAL];

// ---------------------------------------------------------------------------
// family-safe tensor-core + cp.async primitives (sm_80+)
// ---------------------------------------------------------------------------
__device__ __forceinline__ uint32_t smem_to_u32(const void* p) {
    uint32_t a;
    asm("{ .reg .u64 t; cvta.to.shared.u64 t, %1; cvt.u32.u64 %0, t; }" : "=r"(a) : "l"(p));
    return a;
}
__device__ __forceinline__ void ldsm_x4(uint32_t* r, uint32_t addr) {
    asm volatile("ldmatrix.sync.aligned.m8n8.x4.shared.b16 {%0,%1,%2,%3}, [%4];"
                 : "=r"(r[0]), "=r"(r[1]), "=r"(r[2]), "=r"(r[3]) : "r"(addr));
}
__device__ __forceinline__ void ldsm_x4_trans(uint32_t* r, uint32_t addr) {
    asm volatile("ldmatrix.sync.aligned.m8n8.x4.trans.shared.b16 {%0,%1,%2,%3}, [%4];"
                 : "=r"(r[0]), "=r"(r[1]), "=r"(r[2]), "=r"(r[3]) : "r"(addr));
}
__device__ __forceinline__ void mma_bf16(float* c, const uint32_t* a, const uint32_t* b) {
    asm volatile(
        "mma.sync.aligned.m16n8k16.row.col.f32.bf16.bf16.f32 "
        "{%0,%1,%2,%3}, {%4,%5,%6,%7}, {%8,%9}, {%0,%1,%2,%3};"
        : "+f"(c[0]), "+f"(c[1]), "+f"(c[2]), "+f"(c[3])
        : "r"(a[0]), "r"(a[1]), "r"(a[2]), "r"(a[3]), "r"(b[0]), "r"(b[1]));
}
__device__ __forceinline__ void cp16(uint32_t saddr, const void* g) {
    asm volatile("cp.async.cg.shared.global [%0], [%1], 16;" :: "r"(saddr), "l"(g));
}
#define CP_COMMIT() asm volatile("cp.async.commit_group;" ::: "memory")
#define CP_WAIT0()  asm volatile("cp.async.wait_group 0;" ::: "memory")

__device__ __forceinline__ void split2(float v, __nv_bfloat16& h, __nv_bfloat16& l) {
    h = __float2bfloat16(v);
    l = __float2bfloat16(v - __bfloat162float(h));
}

// ---------------------------------------------------------------------------
// Block reduce (256 threads = 8 warps)
// ---------------------------------------------------------------------------
__device__ __forceinline__ float blockReduceSum(float v, float* sbuf) {
    int lane = threadIdx.x & 31, wid = threadIdx.x >> 5;
    #pragma unroll
    for (int o = 16; o; o >>= 1) v += __shfl_xor_sync(0xffffffffu, v, o);
    if (lane == 0) sbuf[wid] = v;
    __syncthreads();
    if (wid == 0) {
        float w = (lane < 8) ? sbuf[lane] : 0.0f;
        #pragma unroll
        for (int o = 4; o; o >>= 1) w += __shfl_xor_sync(0xffffffffu, w, o);
        if (lane == 0) sbuf[0] = w;
    }
    __syncthreads();
    float r = sbuf[0];
    __syncthreads();
    return r;
}

// ---------------------------------------------------------------------------
// LayerNorm (torch-style) + optional bf16 hi/lo split outputs
// ---------------------------------------------------------------------------
__global__ void ln_kernel(const float* __restrict__ X,
                          const float* __restrict__ alpha,
                          const float* __restrict__ beta,
                          float* __restrict__ Y,
                          __nv_bfloat16* __restrict__ Yh,
                          __nv_bfloat16* __restrict__ Yl) {
    __shared__ float sbuf[8];
    size_t row = blockIdx.x;
    const float4* x4 = (const float4*)(X + row * D_);
    float4 xv = x4[threadIdx.x];
    float s = blockReduceSum(xv.x + xv.y + xv.z + xv.w, sbuf);
    float mu = s * (1.0f / D_);
    float d0 = xv.x - mu, d1 = xv.y - mu, d2 = xv.z - mu, d3 = xv.w - mu;
    float ssq = blockReduceSum(d0*d0 + d1*d1 + d2*d2 + d3*d3, sbuf);
    float inv = 1.0f / (sqrtf(ssq * (1.0f / (D_ - 1))) + 1e-6f);
    float4 a = ((const float4*)alpha)[threadIdx.x];
    float4 b = ((const float4*)beta)[threadIdx.x];
    float4 o;
    o.x = a.x * d0 * inv + b.x;
    o.y = a.y * d1 * inv + b.y;
    o.z = a.z * d2 * inv + b.z;
    o.w = a.w * d3 * inv + b.w;
    ((float4*)(Y + row * D_))[threadIdx.x] = o;
    if (Yh) {
        __nv_bfloat16 h0,l0,h1,l1,h2,l2,h3,l3;
        split2(o.x, h0, l0); split2(o.y, h1, l1);
        split2(o.z, h2, l2); split2(o.w, h3, l3);
        size_t off = row * D_ + threadIdx.x * 4;
        __nv_bfloat162* ph = (__nv_bfloat162*)(Yh + off);
        __nv_bfloat162* pl = (__nv_bfloat162*)(Yl + off);
        ph[0] = __nv_bfloat162(h0, h1); ph[1] = __nv_bfloat162(h2, h3);
        pl[0] = __nv_bfloat162(l0, l1); pl[1] = __nv_bfloat162(l2, l3);
    }
}

// ---------------------------------------------------------------------------
// Elementwise split: X (rows x ncols, contiguous) -> H/L with row stride ldout
// ---------------------------------------------------------------------------
__global__ void split_kernel(const float* __restrict__ X,
                             __nv_bfloat16* __restrict__ H,
                             __nv_bfloat16* __restrict__ L,
                             int ncols, int ldout, size_t total) {
    size_t i = (size_t)blockIdx.x * blockDim.x + threadIdx.x;
    if (i >= total) return;
    size_t r = i / ncols;
    int c = (int)(i - r * ncols);
    float v = X[i];
    __nv_bfloat16 h, l;
    split2(v, h, l);
    H[r * ldout + c] = h;
    L[r * ldout + c] = l;
}

// ---------------------------------------------------------------------------
// Transpose + split: W [K x N] row-major -> Th/Tl [N x K]
// ---------------------------------------------------------------------------
__global__ void tsplit_kernel(const float* __restrict__ W,
                              __nv_bfloat16* __restrict__ Th,
                              __nv_bfloat16* __restrict__ Tl,
                              int K, int N) {
    __shared__ float s[32][33];
    int nt = blockIdx.x * 32, kt = blockIdx.y * 32;
    int tx = threadIdx.x, ty = threadIdx.y;
    #pragma unroll
    for (int i = 0; i < 4; i++)
        s[ty + i * 8][tx] = W[(size_t)(kt + ty + i * 8) * N + nt + tx];
    __syncthreads();
    #pragma unroll
    for (int i = 0; i < 4; i++) {
        int n = nt + ty + i * 8;
        int k = kt + tx;
        float v = s[tx][ty + i * 8];
        __nv_bfloat16 h, l;
        split2(v, h, l);
        Th[(size_t)n * K + k] = h;
        Tl[(size_t)n * K + k] = l;
    }
}

// ---------------------------------------------------------------------------
// mma.sync bf16x3 GEMM, 2-stage cp.async pipeline.
// C[MxN] = (Ah+Al)[MxK] @ ((Bh+Bl)[NxK])^T, CTA 128x128, K chunk 64.
// smem: 2 stages x {Ah,Al,Bh,Bl} 16KB each = 128KB.
// ---------------------------------------------------------------------------
#define F_RELU  1
#define F_RESID 2

#define GEMM_SMEM (2 * 4 * 16384)

__global__ void __launch_bounds__(256)
gemm_mma(const __nv_bfloat16* __restrict__ Ah, const __nv_bfloat16* __restrict__ Al,
         const __nv_bfloat16* __restrict__ Bh, const __nv_bfloat16* __restrict__ Bl,
         const float* __restrict__ bias, const float* __restrict__ R,
         float* __restrict__ C,
         __nv_bfloat16* __restrict__ Ch, __nv_bfloat16* __restrict__ Cl,
         int M, int N, int K, int ld_split, int flags) {
    extern __shared__ char smem[];
    const uint32_t sbase = smem_to_u32(smem);
    const int tid = threadIdx.x;
    const int wid = tid >> 5, lane = tid & 31;
    const int rowBase = blockIdx.y * 128, colBase = blockIdx.x * 128;
    const int mWarp = wid & 1;
    const int nWarp = wid >> 1;

    float acc[4][4][4];
    #pragma unroll
    for (int i = 0; i < 4; i++)
        #pragma unroll
        for (int j = 0; j < 4; j++)
            #pragma unroll
            for (int t = 0; t < 4; t++) acc[i][j][t] = 0.f;

    const int r  = tid >> 1;
    const int hf = tid & 1;

    auto issue = [&](int stg, int kt) {
        const char* gAh = (const char*)(Ah + (size_t)(rowBase + r) * K + kt);
        const char* gAl = (const char*)(Al + (size_t)(rowBase + r) * K + kt);
        const char* gBh = (const char*)(Bh + (size_t)(colBase + r) * K + kt);
        const char* gBl = (const char*)(Bl + (size_t)(colBase + r) * K + kt);
        uint32_t sb = sbase + (uint32_t)stg * 65536u;
        #pragma unroll
        for (int i = 0; i < 4; i++) {
            int c16 = hf * 4 + i;
            uint32_t bo = (uint32_t)(r * 128) | (uint32_t)((c16 * 16) ^ ((r & 7) << 4));
            cp16(sb + bo,         gAh + c16 * 16);
            cp16(sb + 16384 + bo, gAl + c16 * 16);
            cp16(sb + 32768 + bo, gBh + c16 * 16);
            cp16(sb + 49152 + bo, gBl + c16 * 16);
        }
    };

    const int nIter = K / 64;
    issue(0, 0);
    CP_COMMIT();

    for (int it = 0; it < nIter; it++) {
        CP_WAIT0();
        __syncthreads();
        if (it + 1 < nIter) { issue((it + 1) & 1, (it + 1) * 64); CP_COMMIT(); }

        const uint32_t sb = sbase + (uint32_t)(it & 1) * 65536u;
        #pragma unroll
        for (int kk = 0; kk < 64; kk += 16) {
            uint32_t Ahf[4][4], Alf[4][4], Bhf[4][2], Blf[4][2];
            #pragma unroll
            for (int mi = 0; mi < 4; mi++) {
                int row = mWarp * 64 + mi * 16 + (lane & 15);
                uint32_t ko = (uint32_t)(kk * 2 + ((lane >> 4) << 4));
                uint32_t off = (uint32_t)(row * 128) | (ko ^ ((row & 7) << 4));
                ldsm_x4(Ahf[mi], sb + off);
                ldsm_x4(Alf[mi], sb + 16384 + off);
            }
            // B: two n-blocks per x4 (lanes 0-15 -> block p*2, 16-31 -> p*2+1)
            #pragma unroll
            for (int p = 0; p < 2; p++) {
                int g = lane >> 3;
                int nrow = nWarp * 32 + (p * 2 + (g >> 1)) * 8 + (lane & 7);
                uint32_t ko = (uint32_t)(kk * 2 + ((g & 1) << 4));
                uint32_t off = (uint32_t)(nrow * 128) | (ko ^ ((nrow & 7) << 4));
                uint32_t rh[4], rl[4];
                ldsm_x4(rh, sb + 32768 + off);
                ldsm_x4(rl, sb + 49152 + off);
                Bhf[p*2][0] = rh[0]; Bhf[p*2][1] = rh[1];
                Bhf[p*2+1][0] = rh[2]; Bhf[p*2+1][1] = rh[3];
                Blf[p*2][0] = rl[0]; Blf[p*2][1] = rl[1];
                Blf[p*2+1][0] = rl[2]; Blf[p*2+1][1] = rl[3];
            }
            #pragma unroll
            for (int mi = 0; mi < 4; mi++)
                #pragma unroll
                for (int ni = 0; ni < 4; ni++) {
                    mma_bf16(acc[mi][ni], Ahf[mi], Bhf[ni]);
                    mma_bf16(acc[mi][ni], Ahf[mi], Blf[ni]);
                    mma_bf16(acc[mi][ni], Alf[mi], Bhf[ni]);
                }
        }
    }

    const int fr = lane >> 2;
    const int fc = (lane & 3) * 2;
    #pragma unroll
    for (int mi = 0; mi < 4; mi++) {
        int m0 = rowBase + mWarp * 64 + mi * 16;
        #pragma unroll
        for (int ni = 0; ni < 4; ni++) {
            int n0 = colBase + nWarp * 32 + ni * 8;
            int col = n0 + fc;
            float2 bv = make_float2(0.f, 0.f);
            if (bias) bv = *(const float2*)(bias + col);
            #pragma unroll
            for (int half = 0; half < 2; half++) {
                int row = m0 + fr + half * 8;
                float2 res;
                res.x = acc[mi][ni][half * 2 + 0] + bv.x;
                res.y = acc[mi][ni][half * 2 + 1] + bv.y;
                size_t off = (size_t)row * N + col;
                if (flags & F_RESID) {
                    float2 rv = *(const float2*)(R + off);
                    res.x += rv.x; res.y += rv.y;
                }
                if (flags & F_RELU) {
                    res.x = fmaxf(res.x, 0.f);
                    res.y = fmaxf(res.y, 0.f);
                }
                if (C) *(float2*)(C + off) = res;
                if (Ch) {
                    __nv_bfloat16 h0, l0, h1, l1;
                    split2(res.x, h0, l0);
                    split2(res.y, h1, l1);
                    size_t so = (size_t)row * ld_split + col;
                    *(__nv_bfloat162*)(Ch + so) = __nv_bfloat162(h0, h1);
                    *(__nv_bfloat162*)(Cl + so) = __nv_bfloat162(l0, l1);
                }
            }
        }
    }
}

// ---------------------------------------------------------------------------
// Flash attention, bf16x3 mma.sync, 2-stage cp.async K/V pipeline.
// grid (S_/128, B_*H_), 256 threads (8 warps x 16 q-rows).
// smem: Q 32KB + 2 stages x {Kh,Kl,Vh,Vl} 8KB = 96KB
// ---------------------------------------------------------------------------
#define FLASH_SMEM (32768 + 2 * 32768)

__global__ void __launch_bounds__(256)
flash_mma(const __nv_bfloat16* __restrict__ Qh, const __nv_bfloat16* __restrict__ Ql,
          const __nv_bfloat16* __restrict__ Kh, const __nv_bfloat16* __restrict__ Kl,
          const __nv_bfloat16* __restrict__ Vh, const __nv_bfloat16* __restrict__ Vl,
          __nv_bfloat16* __restrict__ Ch, __nv_bfloat16* __restrict__ Cl) {
    extern __shared__ char smem[];
    const uint32_t sbase = smem_to_u32(smem);
    const int tid = threadIdx.x;
    const int wid = tid >> 5, lane = tid & 31;
    const int b = blockIdx.y >> 4, h = blockIdx.y & 15;
    const int qbase = blockIdx.x * 128;
    const size_t rowBase = (size_t)b * S_;
    const int colOff = h * DH;

    const uint32_t oQh = 0, oQl = 16384;

    auto issueKV = [&](int stg, int kt) {
        int r = tid >> 2, qd = tid & 3;
        const char* gkh = (const char*)(Kh + (rowBase + kt + r) * D_ + colOff);
        const char* gkl = (const char*)(Kl + (rowBase + kt + r) * D_ + colOff);
        const char* gvh = (const char*)(Vh + (rowBase + kt + r) * D_ + colOff);
        const char* gvl = (const char*)(Vl + (rowBase + kt + r) * D_ + colOff);
        uint32_t sb = sbase + 32768u + (uint32_t)stg * 32768u;
        #pragma unroll
        for (int i = 0; i < 2; i++) {
            int c16 = qd * 2 + i;
            uint32_t bo = (uint32_t)(r * 128) | (uint32_t)((c16 * 16) ^ ((r & 7) << 4));
            cp16(sb + bo,         gkh + c16 * 16);
            cp16(sb + 8192 + bo,  gkl + c16 * 16);
            cp16(sb + 16384 + bo, gvh + c16 * 16);
            cp16(sb + 24576 + bo, gvl + c16 * 16);
        }
    };

    // prefetch stage 0 K/V, then load Q with normal stores
    issueKV(0, 0);
    CP_COMMIT();
    {
        int r = tid >> 1, hf = tid & 1;
        const uint4* gqh = (const uint4*)(Qh + (rowBase + qbase + r) * D_ + colOff);
        const uint4* gql = (const uint4*)(Ql + (rowBase + qbase + r) * D_ + colOff);
        #pragma unroll
        for (int i = 0; i < 4; i++) {
            int c16 = hf * 4 + i;
            uint32_t bo = (uint32_t)(r * 128) | (uint32_t)((c16 * 16) ^ ((r & 7) << 4));
            *(uint4*)(smem + oQh + bo) = gqh[c16];
            *(uint4*)(smem + oQl + bo) = gql[c16];
        }
    }
    __syncthreads();

    // hoist Q fragments (per warp, all 4 k-steps)
    uint32_t QhA[4][4], QlA[4][4];
    #pragma unroll
    for (int ks = 0; ks < 4; ks++) {
        int row = wid * 16 + (lane & 15);
        uint32_t ko = (uint32_t)(ks * 32 + ((lane >> 4) << 4));
        uint32_t off = (uint32_t)(row * 128) | (ko ^ ((row & 7) << 4));
        ldsm_x4(QhA[ks], sbase + oQh + off);
        ldsm_x4(QlA[ks], sbase + oQl + off);
    }

    float m0 = -1e30f, m1 = -1e30f, l0 = 0.f, l1 = 0.f;
    float o[8][4];
    #pragma unroll
    for (int nt = 0; nt < 8; nt++)
        #pragma unroll
        for (int j = 0; j < 4; j++) o[nt][j] = 0.f;

    const int nIter = S_ / 64;
    for (int it = 0; it < nIter; it++) {
        CP_WAIT0();
        __syncthreads();
        if (it + 1 < nIter) { issueKV((it + 1) & 1, (it + 1) * 64); CP_COMMIT(); }

        const uint32_t sKh = sbase + 32768u + (uint32_t)(it & 1) * 32768u;
        const uint32_t sKl = sKh + 8192, sVh = sKh + 16384, sVl = sKh + 24576;

        // S = Q @ K^T  (bf16x3); K frags: two n-blocks per x4
        float s[8][4];
        #pragma unroll
        for (int nt = 0; nt < 8; nt++)
            #pragma unroll
            for (int j = 0; j < 4; j++) s[nt][j] = 0.f;
        #pragma unroll
        for (int ks = 0; ks < 4; ks++) {
            #pragma unroll
            for (int p = 0; p < 4; p++) {
                int g = lane >> 3;
                int nrow = (p * 2 + (g >> 1)) * 8 + (lane & 7);
                uint32_t ko = (uint32_t)(ks * 32 + ((g & 1) << 4));
                uint32_t off = (uint32_t)(nrow * 128) | (ko ^ ((nrow & 7) << 4));
                uint32_t rh[4], rl[4];
                ldsm_x4(rh, sKh + off);
                ldsm_x4(rl, sKl + off);
                uint32_t bh0[2] = {rh[0], rh[1]}, bh1[2] = {rh[2], rh[3]};
                uint32_t bl0[2] = {rl[0], rl[1]}, bl1[2] = {rl[2], rl[3]};
                mma_bf16(s[p*2],   QhA[ks], bh0);
                mma_bf16(s[p*2],   QhA[ks], bl0);
                mma_bf16(s[p*2],   QlA[ks], bh0);
                mma_bf16(s[p*2+1], QhA[ks], bh1);
                mma_bf16(s[p*2+1], QhA[ks], bl1);
                mma_bf16(s[p*2+1], QlA[ks], bh1);
            }
        }

        // online softmax on fragments
        float tm0 = -1e30f, tm1 = -1e30f;
        #pragma unroll
        for (int nt = 0; nt < 8; nt++) {
            #pragma unroll
            for (int j = 0; j < 4; j++) s[nt][j] *= 0.125f;
            tm0 = fmaxf(tm0, fmaxf(s[nt][0], s[nt][1]));
            tm1 = fmaxf(tm1, fmaxf(s[nt][2], s[nt][3]));
        }
        tm0 = fmaxf(tm0, __shfl_xor_sync(0xffffffffu, tm0, 1));
        tm0 = fmaxf(tm0, __shfl_xor_sync(0xffffffffu, tm0, 2));
        tm1 = fmaxf(tm1, __shfl_xor_sync(0xffffffffu, tm1, 1));
        tm1 = fmaxf(tm1, __shfl_xor_sync(0xffffffffu, tm1, 2));
        float mn0 = fmaxf(m0, tm0), mn1 = fmaxf(m1, tm1);
        float sc0 = __expf(m0 - mn0), sc1 = __expf(m1 - mn1);
        float rs0 = 0.f, rs1 = 0.f;
        #pragma unroll
        for (int nt = 0; nt < 8; nt++) {
            s[nt][0] = __expf(s[nt][0] - mn0);
            s[nt][1] = __expf(s[nt][1] - mn0);
            s[nt][2] = __expf(s[nt][2] - mn1);
            s[nt][3] = __expf(s[nt][3] - mn1);
            rs0 += s[nt][0] + s[nt][1];
            rs1 += s[nt][2] + s[nt][3];
        }
        rs0 += __shfl_xor_sync(0xffffffffu, rs0, 1);
        rs0 += __shfl_xor_sync(0xffffffffu, rs0, 2);
        rs1 += __shfl_xor_sync(0xffffffffu, rs1, 1);
        rs1 += __shfl_xor_sync(0xffffffffu, rs1, 2);
        l0 = l0 * sc0 + rs0;
        l1 = l1 * sc1 + rs1;
        m0 = mn0; m1 = mn1;
        #pragma unroll
        for (int nt = 0; nt < 8; nt++) {
            o[nt][0] *= sc0; o[nt][1] *= sc0;
            o[nt][2] *= sc1; o[nt][3] *= sc1;
        }

        // P fragments (C-layout -> A-layout), hi/lo split
        uint32_t PhA[4][4], PlA[4][4];
        #pragma unroll
        for (int ks = 0; ks < 4; ks++) {
            float* e = s[2 * ks];
            float* q = s[2 * ks + 1];
            __nv_bfloat16 h, l;
            __nv_bfloat16 hh0[4], ll0[4], hh1[4], ll1[4];
            #pragma unroll
            for (int j = 0; j < 4; j++) { split2(e[j], h, l); hh0[j] = h; ll0[j] = l; }
            #pragma unroll
            for (int j = 0; j < 4; j++) { split2(q[j], h, l); hh1[j] = h; ll1[j] = l; }
            __nv_bfloat162 t;
            t = __nv_bfloat162(hh0[0], hh0[1]); PhA[ks][0] = *(uint32_t*)&t;
            t = __nv_bfloat162(hh0[2], hh0[3]); PhA[ks][1] = *(uint32_t*)&t;
            t = __nv_bfloat162(hh1[0], hh1[1]); PhA[ks][2] = *(uint32_t*)&t;
            t = __nv_bfloat162(hh1[2], hh1[3]); PhA[ks][3] = *(uint32_t*)&t;
            t = __nv_bfloat162(ll0[0], ll0[1]); PlA[ks][0] = *(uint32_t*)&t;
            t = __nv_bfloat162(ll0[2], ll0[3]); PlA[ks][1] = *(uint32_t*)&t;
            t = __nv_bfloat162(ll1[0], ll1[1]); PlA[ks][2] = *(uint32_t*)&t;
            t = __nv_bfloat162(ll1[2], ll1[3]); PlA[ks][3] = *(uint32_t*)&t;
        }

        // O += P @ V: V via x4 trans (two nt per load)
        #pragma unroll
        for (int ks = 0; ks < 4; ks++) {
            #pragma unroll
            for (int p = 0; p < 4; p++) {
                int krow = ks * 16 + (lane & 15);
                uint32_t cb = (uint32_t)((p * 2 + (lane >> 4)) * 16);
                uint32_t off = (uint32_t)(krow * 128) | (cb ^ ((krow & 7) << 4));
                uint32_t rh[4], rl[4];
                ldsm_x4_trans(rh, sVh + off);
                ldsm_x4_trans(rl, sVl + off);
                uint32_t bh0[2] = {rh[0], rh[1]}, bh1[2] = {rh[2], rh[3]};
                uint32_t bl0[2] = {rl[0], rl[1]}, bl1[2] = {rl[2], rl[3]};
                mma_bf16(o[p*2],   PhA[ks], bh0);
                mma_bf16(o[p*2],   PhA[ks], bl0);
                mma_bf16(o[p*2],   PlA[ks], bh0);
                mma_bf16(o[p*2+1], PhA[ks], bh1);
                mma_bf16(o[p*2+1], PhA[ks], bl1);
                mma_bf16(o[p*2+1], PlA[ks], bh1);
            }
        }
    }

    // epilogue: normalize, split hi/lo, write ctx
    float inv0 = 1.0f / l0, inv1 = 1.0f / l1;
    int fr = lane >> 2, fc = (lane & 3) * 2;
    int r0 = qbase + wid * 16 + fr;
    #pragma unroll
    for (int nt = 0; nt < 8; nt++) {
        int col = colOff + nt * 8 + fc;
        float v0 = o[nt][0] * inv0, v1 = o[nt][1] * inv0;
        float v2 = o[nt][2] * inv1, v3 = o[nt][3] * inv1;
        __nv_bfloat16 h0,lo0,h1,lo1,h2,lo2,h3,lo3;
        split2(v0, h0, lo0); split2(v1, h1, lo1);
        split2(v2, h2, lo2); split2(v3, h3, lo3);
        size_t off0 = (rowBase + r0) * D_ + col;
        size_t off1 = (rowBase + r0 + 8) * D_ + col;
        *(__nv_bfloat162*)(Ch + off0) = __nv_bfloat162(h0, h1);
        *(__nv_bfloat162*)(Cl + off0) = __nv_bfloat162(lo0, lo1);
        *(__nv_bfloat162*)(Ch + off1) = __nv_bfloat162(h2, h3);
        *(__nv_bfloat162*)(Cl + off1) = __nv_bfloat162(lo2, lo3);
    }
}

// ---------------------------------------------------------------------------
// Launch
// ---------------------------------------------------------------------------
extern "C" void kernel_launch(void* const* d_in, const int* in_sizes, int n_in,
                              void* d_out, int out_size) {
    const float* fx  = (const float*)d_in[0];
    const float* px  = (const float*)d_in[1];
    const float* Wq  = (const float*)d_in[2];
    const float* bq  = (const float*)d_in[3];
    const float* Wk  = (const float*)d_in[4];
    const float* bk  = (const float*)d_in[5];
    const float* Wv  = (const float*)d_in[6];
    const float* bv  = (const float*)d_in[7];
    const float* Wo  = (const float*)d_in[8];
    const float* bo  = (const float*)d_in[9];
    const float* a1  = (const float*)d_in[10];
    const float* be1 = (const float*)d_in[11];
    const float* a2  = (const float*)d_in[12];
    const float* be2 = (const float*)d_in[13];
    const float* W1  = (const float*)d_in[14];
    const float* b1  = (const float*)d_in[15];
    const float* W2  = (const float*)d_in[16];
    const float* b2  = (const float*)d_in[17];
    const float* Wp  = (const float*)d_in[18];
    const float* bp  = (const float*)d_in[19];

    float* scratch = nullptr;
    cudaGetSymbolAddress((void**)&scratch, g_scratch);
    __nv_bfloat16* bf = nullptr;
    cudaGetSymbolAddress((void**)&bf, g_bf16);

    float* xn  = scratch;
    float* x1  = xn + NM;
    float* x2  = x1 + NM;
    float* hh  = x2 + NM;

    __nv_bfloat16 *xnh = bf + OFF_XNH,  *xnl = bf + OFF_XNL;
    __nv_bfloat16 *x2h = bf + OFF_X2H,  *x2l = bf + OFF_X2L;
    __nv_bfloat16 *ctxh= bf + OFF_CTXH, *ctxl= bf + OFF_CTXL;
    __nv_bfloat16 *qh  = bf + OFF_QH,   *ql  = bf + OFF_QL;
    __nv_bfloat16 *kh  = bf + OFF_KH,   *kl  = bf + OFF_KL;
    __nv_bfloat16 *vh  = bf + OFF_VH,   *vl  = bf + OFF_VL;
    __nv_bfloat16 *hhh = bf + OFF_HHH,  *hhl = bf + OFF_HHL;
    __nv_bfloat16 *cath= bf + OFF_CATH, *catl= bf + OFF_CATL;
    __nv_bfloat16 *wqh = bf + OFF_WQH,  *wql = bf + OFF_WQL;
    __nv_bfloat16 *wkh = bf + OFF_WKH,  *wkl = bf + OFF_WKL;
    __nv_bfloat16 *wvh = bf + OFF_WVH,  *wvl = bf + OFF_WVL;
    __nv_bfloat16 *woh = bf + OFF_WOH,  *wol = bf + OFF_WOL;
    __nv_bfloat16 *w1h = bf + OFF_W1H,  *w1l = bf + OFF_W1L;
    __nv_bfloat16 *w2h = bf + OFF_W2H,  *w2l = bf + OFF_W2L;
    __nv_bfloat16 *wph = bf + OFF_WPH,  *wpl = bf + OFF_WPL;

    float* xo = (float*)d_out;
    float* pp = xo + NM;

    cudaFuncSetAttribute(gemm_mma, cudaFuncAttributeMaxDynamicSharedMemorySize, GEMM_SMEM);
    cudaFuncSetAttribute(flash_mma, cudaFuncAttributeMaxDynamicSharedMemorySize, FLASH_SMEM);

    dim3 tb(32, 8);
    tsplit_kernel<<<dim3(D_/32, D_/32), tb>>>(Wq, wqh, wql, D_, D_);
    tsplit_kernel<<<dim3(D_/32, D_/32), tb>>>(Wk, wkh, wkl, D_, D_);
    tsplit_kernel<<<dim3(D_/32, D_/32), tb>>>(Wv, wvh, wvl, D_, D_);
    tsplit_kernel<<<dim3(D_/32, D_/32), tb>>>(Wo, woh, wol, D_, D_);
    tsplit_kernel<<<dim3(DFF_/32, D_/32), tb>>>(W1, w1h, w1l, D_, DFF_);
    tsplit_kernel<<<dim3(D_/32, DFF_/32), tb>>>(W2, w2h, w2l, DFF_, D_);
    tsplit_kernel<<<dim3(P_/32, CATW/32), tb>>>(Wp, wph, wpl, CATW, P_);

    // param_x split into cat buffer columns [D_, D_+P_)
    {
        size_t tot = (size_t)MROWS * P_;
        split_kernel<<<(unsigned)((tot + 255) / 256), 256>>>(
            px, cath + D_, catl + D_, P_, CATW, tot);
    }

    // 1. xn = LN1(fx), + hi/lo
    ln_kernel<<<MROWS, 256>>>(fx, a1, be1, xn, xnh, xnl);

    // 2-4. q/k/v (bf16 hi/lo outputs only)
    gemm_mma<<<dim3(D_/128, MROWS/128), 256, GEMM_SMEM>>>(
        xnh, xnl, wqh, wql, bq, nullptr, nullptr, qh, ql, MROWS, D_, D_, D_, 0);
    gemm_mma<<<dim3(D_/128, MROWS/128), 256, GEMM_SMEM>>>(
        xnh, xnl, wkh, wkl, bk, nullptr, nullptr, kh, kl, MROWS, D_, D_, D_, 0);
    gemm_mma<<<dim3(D_/128, MROWS/128), 256, GEMM_SMEM>>>(
        xnh, xnl, wvh, wvl, bv, nullptr, nullptr, vh, vl, MROWS, D_, D_, D_, 0);

    // 5. attention (tensor-core flash) -> ctx hi/lo
    flash_mma<<<dim3(S_/128, B_*H_), 256, FLASH_SMEM>>>(qh, ql, kh, kl, vh, vl, ctxh, ctxl);

    // 6. x1 = xn + ctx @ Wo + bo
    gemm_mma<<<dim3(D_/128, MROWS/128), 256, GEMM_SMEM>>>(
        ctxh, ctxl, woh, wol, bo, xn, x1, nullptr, nullptr, MROWS, D_, D_, 0, F_RESID);

    // 7. x2 = LN2(x1), + hi/lo
    ln_kernel<<<MROWS, 256>>>(x1, a2, be2, x2, x2h, x2l);

    // 8. hh = relu(x2 @ W1 + b1), + hi/lo
    gemm_mma<<<dim3(DFF_/128, MROWS/128), 256, GEMM_SMEM>>>(
        x2h, x2l, w1h, w1l, b1, nullptr, hh, hhh, hhl, MROWS, DFF_, D_, DFF_, F_RELU);

    // 9. x = x1 + hh @ W2 + b2 -> d_out, + split into cat[:, 0:D]
    gemm_mma<<<dim3(D_/128, MROWS/128), 256, GEMM_SMEM>>>(
        hhh, hhl, w2h, w2l, b2, x1, xo, cath, catl, MROWS, D_, DFF_, CATW, F_RESID);

    // 10. p = [x | px] @ Wp + bp   (single K=1280 GEMM)
    gemm_mma<<<dim3(P_/128, MROWS/128), 256, GEMM_SMEM>>>(
        cath, catl, wph, wpl, bp, nullptr, pp, nullptr, nullptr, MROWS, P_, CATW, 0, 0);
}

// round 6
// speedup vs baseline: 3.1465x; 1.0428x over previous
#include <cuda_runtime.h>
#include <cuda_bf16.h>
#include <math.h>
#include <stdint.h>

#define B_    4
#define S_    2048
#define D_    1024
#define H_    16
#define DH    64
#define DFF_  512
#define P_    256
#define MROWS (B_*S_)          // 8192
#define CATW  (D_ + P_)        // 1280
#define QKVW  (3*D_)           // 3072

#define NM  ((size_t)MROWS * D_)      // 8388608
#define NH  ((size_t)MROWS * DFF_)    // 4194304
#define NC  ((size_t)MROWS * CATW)    // 10485760
#define NQKV ((size_t)MROWS * QKVW)   // 25165824
#define DD  ((size_t)D_*D_)

// fp32 scratch: xn, x1, x2 (NM each) + hh (NH)
__device__ float g_scratch[3 * NM + NH];
__device__ float g_bqkv[QKVW];

// bf16 scratch
#define OFF_XNH   ((size_t)0)
#define OFF_XNL   (OFF_XNH + NM)
#define OFF_X2H   (OFF_XNL + NM)
#define OFF_X2L   (OFF_X2H + NM)
#define OFF_CTXH  (OFF_X2L + NM)
#define OFF_CTXL  (OFF_CTXH + NM)
#define OFF_QKVH  (OFF_CTXL + NM)
#define OFF_QKVL  (OFF_QKVH + NQKV)
#define OFF_HHH   (OFF_QKVL + NQKV)
#define OFF_HHL   (OFF_HHH + NH)
#define OFF_CATH  (OFF_HHL + NH)
#define OFF_CATL  (OFF_CATH + NC)
#define OFF_WQKVH (OFF_CATL + NC)
#define OFF_WQKVL (OFF_WQKVH + 3*DD)
#define OFF_WOH   (OFF_WQKVL + 3*DD)
#define OFF_WOL   (OFF_WOH + DD)
#define OFF_W1H   (OFF_WOL + DD)
#define OFF_W1L   (OFF_W1H + (size_t)D_*DFF_)
#define OFF_W2H   (OFF_W1L + (size_t)D_*DFF_)
#define OFF_W2L   (OFF_W2H + (size_t)D_*DFF_)
#define OFF_WPH   (OFF_W2L + (size_t)D_*DFF_)
#define OFF_WPL   (OFF_WPH + (size_t)CATW*P_)
#define BF_TOTAL  (OFF_WPL + (size_t)CATW*P_)

__device__ __nv_bfloat16 g_bf16[BF_TOTAL];

// ---------------------------------------------------------------------------
// primitives (sm_80+ family-safe)
// ---------------------------------------------------------------------------
__device__ __forceinline__ uint32_t smem_to_u32(const void* p) {
    uint32_t a;
    asm("{ .reg .u64 t; cvta.to.shared.u64 t, %1; cvt.u32.u64 %0, t; }" : "=r"(a) : "l"(p));
    return a;
}
__device__ __forceinline__ void ldsm_x4(uint32_t* r, uint32_t addr) {
    asm volatile("ldmatrix.sync.aligned.m8n8.x4.shared.b16 {%0,%1,%2,%3}, [%4];"
                 : "=r"(r[0]), "=r"(r[1]), "=r"(r[2]), "=r"(r[3]) : "r"(addr));
}
__device__ __forceinline__ void ldsm_x4_trans(uint32_t* r, uint32_t addr) {
    asm volatile("ldmatrix.sync.aligned.m8n8.x4.trans.shared.b16 {%0,%1,%2,%3}, [%4];"
                 : "=r"(r[0]), "=r"(r[1]), "=r"(r[2]), "=r"(r[3]) : "r"(addr));
}
__device__ __forceinline__ void mma_bf16(float* c, const uint32_t* a, const uint32_t* b) {
    asm volatile(
        "mma.sync.aligned.m16n8k16.row.col.f32.bf16.bf16.f32 "
        "{%0,%1,%2,%3}, {%4,%5,%6,%7}, {%8,%9}, {%0,%1,%2,%3};"
        : "+f"(c[0]), "+f"(c[1]), "+f"(c[2]), "+f"(c[3])
        : "r"(a[0]), "r"(a[1]), "r"(a[2]), "r"(a[3]), "r"(b[0]), "r"(b[1]));
}
__device__ __forceinline__ void cp16(uint32_t saddr, const void* g) {
    asm volatile("cp.async.cg.shared.global [%0], [%1], 16;" :: "r"(saddr), "l"(g));
}
#define CP_COMMIT() asm volatile("cp.async.commit_group;" ::: "memory")
#define CP_WAIT0()  asm volatile("cp.async.wait_group 0;" ::: "memory")

__device__ __forceinline__ void split2(float v, __nv_bfloat16& h, __nv_bfloat16& l) {
    h = __float2bfloat16(v);
    l = __float2bfloat16(v - __bfloat162float(h));
}

// ---------------------------------------------------------------------------
__device__ __forceinline__ float blockReduceSum(float v, float* sbuf) {
    int lane = threadIdx.x & 31, wid = threadIdx.x >> 5;
    #pragma unroll
    for (int o = 16; o; o >>= 1) v += __shfl_xor_sync(0xffffffffu, v, o);
    if (lane == 0) sbuf[wid] = v;
    __syncthreads();
    if (wid == 0) {
        float w = (lane < 8) ? sbuf[lane] : 0.0f;
        #pragma unroll
        for (int o = 4; o; o >>= 1) w += __shfl_xor_sync(0xffffffffu, w, o);
        if (lane == 0) sbuf[0] = w;
    }
    __syncthreads();
    float r = sbuf[0];
    __syncthreads();
    return r;
}

__global__ void ln_kernel(const float* __restrict__ X,
                          const float* __restrict__ alpha,
                          const float* __restrict__ beta,
                          float* __restrict__ Y,
                          __nv_bfloat16* __restrict__ Yh,
                          __nv_bfloat16* __restrict__ Yl) {
    __shared__ float sbuf[8];
    size_t row = blockIdx.x;
    const float4* x4 = (const float4*)(X + row * D_);
    float4 xv = x4[threadIdx.x];
    float s = blockReduceSum(xv.x + xv.y + xv.z + xv.w, sbuf);
    float mu = s * (1.0f / D_);
    float d0 = xv.x - mu, d1 = xv.y - mu, d2 = xv.z - mu, d3 = xv.w - mu;
    float ssq = blockReduceSum(d0*d0 + d1*d1 + d2*d2 + d3*d3, sbuf);
    float inv = 1.0f / (sqrtf(ssq * (1.0f / (D_ - 1))) + 1e-6f);
    float4 a = ((const float4*)alpha)[threadIdx.x];
    float4 b = ((const float4*)beta)[threadIdx.x];
    float4 o;
    o.x = a.x * d0 * inv + b.x;
    o.y = a.y * d1 * inv + b.y;
    o.z = a.z * d2 * inv + b.z;
    o.w = a.w * d3 * inv + b.w;
    ((float4*)(Y + row * D_))[threadIdx.x] = o;
    if (Yh) {
        __nv_bfloat16 h0,l0,h1,l1,h2,l2,h3,l3;
        split2(o.x, h0, l0); split2(o.y, h1, l1);
        split2(o.z, h2, l2); split2(o.w, h3, l3);
        size_t off = row * D_ + threadIdx.x * 4;
        __nv_bfloat162* ph = (__nv_bfloat162*)(Yh + off);
        __nv_bfloat162* pl = (__nv_bfloat162*)(Yl + off);
        ph[0] = __nv_bfloat162(h0, h1); ph[1] = __nv_bfloat162(h2, h3);
        pl[0] = __nv_bfloat162(l0, l1); pl[1] = __nv_bfloat162(l2, l3);
    }
}

__global__ void split_kernel(const float* __restrict__ X,
                             __nv_bfloat16* __restrict__ H,
                             __nv_bfloat16* __restrict__ L,
                             int ncols, int ldout, size_t total) {
    size_t i = (size_t)blockIdx.x * blockDim.x + threadIdx.x;
    if (i >= total) return;
    size_t r = i / ncols;
    int c = (int)(i - r * ncols);
    float v = X[i];
    __nv_bfloat16 h, l;
    split2(v, h, l);
    H[r * ldout + c] = h;
    L[r * ldout + c] = l;
}

__global__ void biascat_kernel(const float* __restrict__ bq,
                               const float* __restrict__ bk,
                               const float* __restrict__ bv,
                               float* __restrict__ out) {
    int i = blockIdx.x * blockDim.x + threadIdx.x;
    if (i < D_) out[i] = bq[i];
    else if (i < 2 * D_) out[i] = bk[i - D_];
    else if (i < 3 * D_) out[i] = bv[i - 2 * D_];
}

// Transpose + split: W [K x N] row-major -> Th/Tl [N x K]
__global__ void tsplit_kernel(const float* __restrict__ W,
                              __nv_bfloat16* __restrict__ Th,
                              __nv_bfloat16* __restrict__ Tl,
                              int K, int N) {
    __shared__ float s[32][33];
    int nt = blockIdx.x * 32, kt = blockIdx.y * 32;
    int tx = threadIdx.x, ty = threadIdx.y;
    #pragma unroll
    for (int i = 0; i < 4; i++)
        s[ty + i * 8][tx] = W[(size_t)(kt + ty + i * 8) * N + nt + tx];
    __syncthreads();
    #pragma unroll
    for (int i = 0; i < 4; i++) {
        int n = nt + ty + i * 8;
        int k = kt + tx;
        float v = s[tx][ty + i * 8];
        __nv_bfloat16 h, l;
        split2(v, h, l);
        Th[(size_t)n * K + k] = h;
        Tl[(size_t)n * K + k] = l;
    }
}

// Batched D_xD_ transpose+split (4 weights via blockIdx.z)
__global__ void tsplit4_kernel(const float* __restrict__ W0, const float* __restrict__ W1,
                               const float* __restrict__ W2, const float* __restrict__ W3,
                               __nv_bfloat16* __restrict__ T0h, __nv_bfloat16* __restrict__ T0l,
                               __nv_bfloat16* __restrict__ T1h, __nv_bfloat16* __restrict__ T1l,
                               __nv_bfloat16* __restrict__ T2h, __nv_bfloat16* __restrict__ T2l,
                               __nv_bfloat16* __restrict__ T3h, __nv_bfloat16* __restrict__ T3l) {
    __shared__ float s[32][33];
    int z = blockIdx.z;
    const float* W = (z == 0) ? W0 : (z == 1) ? W1 : (z == 2) ? W2 : W3;
    __nv_bfloat16* Th = (z == 0) ? T0h : (z == 1) ? T1h : (z == 2) ? T2h : T3h;
    __nv_bfloat16* Tl = (z == 0) ? T0l : (z == 1) ? T1l : (z == 2) ? T2l : T3l;
    int nt = blockIdx.x * 32, kt = blockIdx.y * 32;
    int tx = threadIdx.x, ty = threadIdx.y;
    #pragma unroll
    for (int i = 0; i < 4; i++)
        s[ty + i * 8][tx] = W[(size_t)(kt + ty + i * 8) * D_ + nt + tx];
    __syncthreads();
    #pragma unroll
    for (int i = 0; i < 4; i++) {
        int n = nt + ty + i * 8;
        int k = kt + tx;
        float v = s[tx][ty + i * 8];
        __nv_bfloat16 h, l;
        split2(v, h, l);
        Th[(size_t)n * D_ + k] = h;
        Tl[(size_t)n * D_ + k] = l;
    }
}

// ---------------------------------------------------------------------------
// mma.sync bf16x3 GEMM, 2-stage cp.async pipeline (as R5)
// ---------------------------------------------------------------------------
#define F_RELU  1
#define F_RESID 2

#define GEMM_SMEM (2 * 4 * 16384)

__global__ void __launch_bounds__(256)
gemm_mma(const __nv_bfloat16* __restrict__ Ah, const __nv_bfloat16* __restrict__ Al,
         const __nv_bfloat16* __restrict__ Bh, const __nv_bfloat16* __restrict__ Bl,
         const float* __restrict__ bias, const float* __restrict__ R,
         float* __restrict__ C,
         __nv_bfloat16* __restrict__ Ch, __nv_bfloat16* __restrict__ Cl,
         int M, int N, int K, int ld_split, int flags) {
    extern __shared__ char smem[];
    const uint32_t sbase = smem_to_u32(smem);
    const int tid = threadIdx.x;
    const int wid = tid >> 5, lane = tid & 31;
    const int rowBase = blockIdx.y * 128, colBase = blockIdx.x * 128;
    const int mWarp = wid & 1;
    const int nWarp = wid >> 1;

    float acc[4][4][4];
    #pragma unroll
    for (int i = 0; i < 4; i++)
        #pragma unroll
        for (int j = 0; j < 4; j++)
            #pragma unroll
            for (int t = 0; t < 4; t++) acc[i][j][t] = 0.f;

    const int r  = tid >> 1;
    const int hf = tid & 1;

    auto issue = [&](int stg, int kt) {
        const char* gAh = (const char*)(Ah + (size_t)(rowBase + r) * K + kt);
        const char* gAl = (const char*)(Al + (size_t)(rowBase + r) * K + kt);
        const char* gBh = (const char*)(Bh + (size_t)(colBase + r) * K + kt);
        const char* gBl = (const char*)(Bl + (size_t)(colBase + r) * K + kt);
        uint32_t sb = sbase + (uint32_t)stg * 65536u;
        #pragma unroll
        for (int i = 0; i < 4; i++) {
            int c16 = hf * 4 + i;
            uint32_t bo = (uint32_t)(r * 128) | (uint32_t)((c16 * 16) ^ ((r & 7) << 4));
            cp16(sb + bo,         gAh + c16 * 16);
            cp16(sb + 16384 + bo, gAl + c16 * 16);
            cp16(sb + 32768 + bo, gBh + c16 * 16);
            cp16(sb + 49152 + bo, gBl + c16 * 16);
        }
    };

    const int nIter = K / 64;
    issue(0, 0);
    CP_COMMIT();

    for (int it = 0; it < nIter; it++) {
        CP_WAIT0();
        __syncthreads();
        if (it + 1 < nIter) { issue((it + 1) & 1, (it + 1) * 64); CP_COMMIT(); }

        const uint32_t sb = sbase + (uint32_t)(it & 1) * 65536u;
        #pragma unroll
        for (int kk = 0; kk < 64; kk += 16) {
            uint32_t Ahf[4][4], Alf[4][4], Bhf[4][2], Blf[4][2];
            #pragma unroll
            for (int mi = 0; mi < 4; mi++) {
                int row = mWarp * 64 + mi * 16 + (lane & 15);
                uint32_t ko = (uint32_t)(kk * 2 + ((lane >> 4) << 4));
                uint32_t off = (uint32_t)(row * 128) | (ko ^ ((row & 7) << 4));
                ldsm_x4(Ahf[mi], sb + off);
                ldsm_x4(Alf[mi], sb + 16384 + off);
            }
            #pragma unroll
            for (int p = 0; p < 2; p++) {
                int g = lane >> 3;
                int nrow = nWarp * 32 + (p * 2 + (g >> 1)) * 8 + (lane & 7);
                uint32_t ko = (uint32_t)(kk * 2 + ((g & 1) << 4));
                uint32_t off = (uint32_t)(nrow * 128) | (ko ^ ((nrow & 7) << 4));
                uint32_t rh[4], rl[4];
                ldsm_x4(rh, sb + 32768 + off);
                ldsm_x4(rl, sb + 49152 + off);
                Bhf[p*2][0] = rh[0]; Bhf[p*2][1] = rh[1];
                Bhf[p*2+1][0] = rh[2]; Bhf[p*2+1][1] = rh[3];
                Blf[p*2][0] = rl[0]; Blf[p*2][1] = rl[1];
                Blf[p*2+1][0] = rl[2]; Blf[p*2+1][1] = rl[3];
            }
            #pragma unroll
            for (int mi = 0; mi < 4; mi++)
                #pragma unroll
                for (int ni = 0; ni < 4; ni++) {
                    mma_bf16(acc[mi][ni], Ahf[mi], Bhf[ni]);
                    mma_bf16(acc[mi][ni], Ahf[mi], Blf[ni]);
                    mma_bf16(acc[mi][ni], Alf[mi], Bhf[ni]);
                }
        }
    }

    const int fr = lane >> 2;
    const int fc = (lane & 3) * 2;
    #pragma unroll
    for (int mi = 0; mi < 4; mi++) {
        int m0 = rowBase + mWarp * 64 + mi * 16;
        #pragma unroll
        for (int ni = 0; ni < 4; ni++) {
            int n0 = colBase + nWarp * 32 + ni * 8;
            int col = n0 + fc;
            float2 bv = make_float2(0.f, 0.f);
            if (bias) bv = *(const float2*)(bias + col);
            #pragma unroll
            for (int half = 0; half < 2; half++) {
                int row = m0 + fr + half * 8;
                float2 res;
                res.x = acc[mi][ni][half * 2 + 0] + bv.x;
                res.y = acc[mi][ni][half * 2 + 1] + bv.y;
                size_t off = (size_t)row * N + col;
                if (flags & F_RESID) {
                    float2 rv = *(const float2*)(R + off);
                    res.x += rv.x; res.y += rv.y;
                }
                if (flags & F_RELU) {
                    res.x = fmaxf(res.x, 0.f);
                    res.y = fmaxf(res.y, 0.f);
                }
                if (C) *(float2*)(C + off) = res;
                if (Ch) {
                    __nv_bfloat16 h0, l0, h1, l1;
                    split2(res.x, h0, l0);
                    split2(res.y, h1, l1);
                    size_t so = (size_t)row * ld_split + col;
                    *(__nv_bfloat162*)(Ch + so) = __nv_bfloat162(h0, h1);
                    *(__nv_bfloat162*)(Cl + so) = __nv_bfloat162(l0, l1);
                }
            }
        }
    }
}

// ---------------------------------------------------------------------------
// Flash attention over fused QKV buffer (row stride 3072).
// q cols [h*64, h*64+64), k cols +1024, v cols +2048.
// ---------------------------------------------------------------------------
#define FLASH_SMEM (32768 + 2 * 32768)

__global__ void __launch_bounds__(256)
flash_mma(const __nv_bfloat16* __restrict__ QKVh, const __nv_bfloat16* __restrict__ QKVl,
          __nv_bfloat16* __restrict__ Ch, __nv_bfloat16* __restrict__ Cl) {
    extern __shared__ char smem[];
    const uint32_t sbase = smem_to_u32(smem);
    const int tid = threadIdx.x;
    const int wid = tid >> 5, lane = tid & 31;
    const int b = blockIdx.y >> 4, h = blockIdx.y & 15;
    const int qbase = blockIdx.x * 128;
    const size_t rowBase = (size_t)b * S_;
    const int colOff = h * DH;

    const uint32_t oQh = 0, oQl = 16384;

    auto issueKV = [&](int stg, int kt) {
        int r = tid >> 2, qd = tid & 3;
        const char* gkh = (const char*)(QKVh + (rowBase + kt + r) * QKVW + D_ + colOff);
        const char* gkl = (const char*)(QKVl + (rowBase + kt + r) * QKVW + D_ + colOff);
        const char* gvh = (const char*)(QKVh + (rowBase + kt + r) * QKVW + 2 * D_ + colOff);
        const char* gvl = (const char*)(QKVl + (rowBase + kt + r) * QKVW + 2 * D_ + colOff);
        uint32_t sb = sbase + 32768u + (uint32_t)stg * 32768u;
        #pragma unroll
        for (int i = 0; i < 2; i++) {
            int c16 = qd * 2 + i;
            uint32_t bo = (uint32_t)(r * 128) | (uint32_t)((c16 * 16) ^ ((r & 7) << 4));
            cp16(sb + bo,         gkh + c16 * 16);
            cp16(sb + 8192 + bo,  gkl + c16 * 16);
            cp16(sb + 16384 + bo, gvh + c16 * 16);
            cp16(sb + 24576 + bo, gvl + c16 * 16);
        }
    };

    issueKV(0, 0);
    CP_COMMIT();
    {
        int r = tid >> 1, hf = tid & 1;
        const uint4* gqh = (const uint4*)(QKVh + (rowBase + qbase + r) * QKVW + colOff);
        const uint4* gql = (const uint4*)(QKVl + (rowBase + qbase + r) * QKVW + colOff);
        #pragma unroll
        for (int i = 0; i < 4; i++) {
            int c16 = hf * 4 + i;
            uint32_t bo = (uint32_t)(r * 128) | (uint32_t)((c16 * 16) ^ ((r & 7) << 4));
            *(uint4*)(smem + oQh + bo) = gqh[c16];
            *(uint4*)(smem + oQl + bo) = gql[c16];
        }
    }
    __syncthreads();

    uint32_t QhA[4][4], QlA[4][4];
    #pragma unroll
    for (int ks = 0; ks < 4; ks++) {
        int row = wid * 16 + (lane & 15);
        uint32_t ko = (uint32_t)(ks * 32 + ((lane >> 4) << 4));
        uint32_t off = (uint32_t)(row * 128) | (ko ^ ((row & 7) << 4));
        ldsm_x4(QhA[ks], sbase + oQh + off);
        ldsm_x4(QlA[ks], sbase + oQl + off);
    }

    float m0 = -1e30f, m1 = -1e30f, l0 = 0.f, l1 = 0.f;
    float o[8][4];
    #pragma unroll
    for (int nt = 0; nt < 8; nt++)
        #pragma unroll
        for (int j = 0; j < 4; j++) o[nt][j] = 0.f;

    const int nIter = S_ / 64;
    for (int it = 0; it < nIter; it++) {
        CP_WAIT0();
        __syncthreads();
        if (it + 1 < nIter) { issueKV((it + 1) & 1, (it + 1) * 64); CP_COMMIT(); }

        const uint32_t sKh = sbase + 32768u + (uint32_t)(it & 1) * 32768u;
        const uint32_t sKl = sKh + 8192, sVh = sKh + 16384, sVl = sKh + 24576;

        float s[8][4];
        #pragma unroll
        for (int nt = 0; nt < 8; nt++)
            #pragma unroll
            for (int j = 0; j < 4; j++) s[nt][j] = 0.f;
        #pragma unroll
        for (int ks = 0; ks < 4; ks++) {
            #pragma unroll
            for (int p = 0; p < 4; p++) {
                int g = lane >> 3;
                int nrow = (p * 2 + (g >> 1)) * 8 + (lane & 7);
                uint32_t ko = (uint32_t)(ks * 32 + ((g & 1) << 4));
                uint32_t off = (uint32_t)(nrow * 128) | (ko ^ ((nrow & 7) << 4));
                uint32_t rh[4], rl[4];
                ldsm_x4(rh, sKh + off);
                ldsm_x4(rl, sKl + off);
                uint32_t bh0[2] = {rh[0], rh[1]}, bh1[2] = {rh[2], rh[3]};
                uint32_t bl0[2] = {rl[0], rl[1]}, bl1[2] = {rl[2], rl[3]};
                mma_bf16(s[p*2],   QhA[ks], bh0);
                mma_bf16(s[p*2],   QhA[ks], bl0);
                mma_bf16(s[p*2],   QlA[ks], bh0);
                mma_bf16(s[p*2+1], QhA[ks], bh1);
                mma_bf16(s[p*2+1], QhA[ks], bl1);
                mma_bf16(s[p*2+1], QlA[ks], bh1);
            }
        }

        float tm0 = -1e30f, tm1 = -1e30f;
        #pragma unroll
        for (int nt = 0; nt < 8; nt++) {
            #pragma unroll
            for (int j = 0; j < 4; j++) s[nt][j] *= 0.125f;
            tm0 = fmaxf(tm0, fmaxf(s[nt][0], s[nt][1]));
            tm1 = fmaxf(tm1, fmaxf(s[nt][2], s[nt][3]));
        }
        tm0 = fmaxf(tm0, __shfl_xor_sync(0xffffffffu, tm0, 1));
        tm0 = fmaxf(tm0, __shfl_xor_sync(0xffffffffu, tm0, 2));
        tm1 = fmaxf(tm1, __shfl_xor_sync(0xffffffffu, tm1, 1));
        tm1 = fmaxf(tm1, __shfl_xor_sync(0xffffffffu, tm1, 2));
        float mn0 = fmaxf(m0, tm0), mn1 = fmaxf(m1, tm1);
        float sc0 = __expf(m0 - mn0), sc1 = __expf(m1 - mn1);
        float rs0 = 0.f, rs1 = 0.f;
        #pragma unroll
        for (int nt = 0; nt < 8; nt++) {
            s[nt][0] = __expf(s[nt][0] - mn0);
            s[nt][1] = __expf(s[nt][1] - mn0);
            s[nt][2] = __expf(s[nt][2] - mn1);
            s[nt][3] = __expf(s[nt][3] - mn1);
            rs0 += s[nt][0] + s[nt][1];
            rs1 += s[nt][2] + s[nt][3];
        }
        rs0 += __shfl_xor_sync(0xffffffffu, rs0, 1);
        rs0 += __shfl_xor_sync(0xffffffffu, rs0, 2);
        rs1 += __shfl_xor_sync(0xffffffffu, rs1, 1);
        rs1 += __shfl_xor_sync(0xffffffffu, rs1, 2);
        l0 = l0 * sc0 + rs0;
        l1 = l1 * sc1 + rs1;
        m0 = mn0; m1 = mn1;
        #pragma unroll
        for (int nt = 0; nt < 8; nt++) {
            o[nt][0] *= sc0; o[nt][1] *= sc0;
            o[nt][2] *= sc1; o[nt][3] *= sc1;
        }

        uint32_t PhA[4][4], PlA[4][4];
        #pragma unroll
        for (int ks = 0; ks < 4; ks++) {
            float* e = s[2 * ks];
            float* q = s[2 * ks + 1];
            __nv_bfloat16 h, l;
            __nv_bfloat16 hh0[4], ll0[4], hh1[4], ll1[4];
            #pragma unroll
            for (int j = 0; j < 4; j++) { split2(e[j], h, l); hh0[j] = h; ll0[j] = l; }
            #pragma unroll
            for (int j = 0; j < 4; j++) { split2(q[j], h, l); hh1[j] = h; ll1[j] = l; }
            __nv_bfloat162 t;
            t = __nv_bfloat162(hh0[0], hh0[1]); PhA[ks][0] = *(uint32_t*)&t;
            t = __nv_bfloat162(hh0[2], hh0[3]); PhA[ks][1] = *(uint32_t*)&t;
            t = __nv_bfloat162(hh1[0], hh1[1]); PhA[ks][2] = *(uint32_t*)&t;
            t = __nv_bfloat162(hh1[2], hh1[3]); PhA[ks][3] = *(uint32_t*)&t;
            t = __nv_bfloat162(ll0[0], ll0[1]); PlA[ks][0] = *(uint32_t*)&t;
            t = __nv_bfloat162(ll0[2], ll0[3]); PlA[ks][1] = *(uint32_t*)&t;
            t = __nv_bfloat162(ll1[0], ll1[1]); PlA[ks][2] = *(uint32_t*)&t;
            t = __nv_bfloat162(ll1[2], ll1[3]); PlA[ks][3] = *(uint32_t*)&t;
        }

        #pragma unroll
        for (int ks = 0; ks < 4; ks++) {
            #pragma unroll
            for (int p = 0; p < 4; p++) {
                int krow = ks * 16 + (lane & 15);
                uint32_t cb = (uint32_t)((p * 2 + (lane >> 4)) * 16);
                uint32_t off = (uint32_t)(krow * 128) | (cb ^ ((krow & 7) << 4));
                uint32_t rh[4], rl[4];
                ldsm_x4_trans(rh, sVh + off);
                ldsm_x4_trans(rl, sVl + off);
                uint32_t bh0[2] = {rh[0], rh[1]}, bh1[2] = {rh[2], rh[3]};
                uint32_t bl0[2] = {rl[0], rl[1]}, bl1[2] = {rl[2], rl[3]};
                mma_bf16(o[p*2],   PhA[ks], bh0);
                mma_bf16(o[p*2],   PhA[ks], bl0);
                mma_bf16(o[p*2],   PlA[ks], bh0);
                mma_bf16(o[p*2+1], PhA[ks], bh1);
                mma_bf16(o[p*2+1], PhA[ks], bl1);
                mma_bf16(o[p*2+1], PlA[ks], bh1);
            }
        }
    }

    float inv0 = 1.0f / l0, inv1 = 1.0f / l1;
    int fr = lane >> 2, fc = (lane & 3) * 2;
    int r0 = qbase + wid * 16 + fr;
    #pragma unroll
    for (int nt = 0; nt < 8; nt++) {
        int col = colOff + nt * 8 + fc;
        float v0 = o[nt][0] * inv0, v1 = o[nt][1] * inv0;
        float v2 = o[nt][2] * inv1, v3 = o[nt][3] * inv1;
        __nv_bfloat16 h0,lo0,h1,lo1,h2,lo2,h3,lo3;
        split2(v0, h0, lo0); split2(v1, h1, lo1);
        split2(v2, h2, lo2); split2(v3, h3, lo3);
        size_t off0 = (rowBase + r0) * D_ + col;
        size_t off1 = (rowBase + r0 + 8) * D_ + col;
        *(__nv_bfloat162*)(Ch + off0) = __nv_bfloat162(h0, h1);
        *(__nv_bfloat162*)(Cl + off0) = __nv_bfloat162(lo0, lo1);
        *(__nv_bfloat162*)(Ch + off1) = __nv_bfloat162(h2, h3);
        *(__nv_bfloat162*)(Cl + off1) = __nv_bfloat162(lo2, lo3);
    }
}

// ---------------------------------------------------------------------------
// Launch
// ---------------------------------------------------------------------------
extern "C" void kernel_launch(void* const* d_in, const int* in_sizes, int n_in,
                              void* d_out, int out_size) {
    const float* fx  = (const float*)d_in[0];
    const float* px  = (const float*)d_in[1];
    const float* Wq  = (const float*)d_in[2];
    const float* bq  = (const float*)d_in[3];
    const float* Wk  = (const float*)d_in[4];
    const float* bk  = (const float*)d_in[5];
    const float* Wv  = (const float*)d_in[6];
    const float* bv  = (const float*)d_in[7];
    const float* Wo  = (const float*)d_in[8];
    const float* bo  = (const float*)d_in[9];
    const float* a1  = (const float*)d_in[10];
    const float* be1 = (const float*)d_in[11];
    const float* a2  = (const float*)d_in[12];
    const float* be2 = (const float*)d_in[13];
    const float* W1  = (const float*)d_in[14];
    const float* b1  = (const float*)d_in[15];
    const float* W2  = (const float*)d_in[16];
    const float* b2  = (const float*)d_in[17];
    const float* Wp  = (const float*)d_in[18];
    const float* bp  = (const float*)d_in[19];

    float* scratch = nullptr;
    cudaGetSymbolAddress((void**)&scratch, g_scratch);
    __nv_bfloat16* bf = nullptr;
    cudaGetSymbolAddress((void**)&bf, g_bf16);
    float* bqkv = nullptr;
    cudaGetSymbolAddress((void**)&bqkv, g_bqkv);

    float* xn  = scratch;
    float* x1  = xn + NM;
    float* x2  = x1 + NM;
    float* hh  = x2 + NM;

    __nv_bfloat16 *xnh  = bf + OFF_XNH,  *xnl  = bf + OFF_XNL;
    __nv_bfloat16 *x2h  = bf + OFF_X2H,  *x2l  = bf + OFF_X2L;
    __nv_bfloat16 *ctxh = bf + OFF_CTXH, *ctxl = bf + OFF_CTXL;
    __nv_bfloat16 *qkvh = bf + OFF_QKVH, *qkvl = bf + OFF_QKVL;
    __nv_bfloat16 *hhh  = bf + OFF_HHH,  *hhl  = bf + OFF_HHL;
    __nv_bfloat16 *cath = bf + OFF_CATH, *catl = bf + OFF_CATL;
    __nv_bfloat16 *wqkvh= bf + OFF_WQKVH,*wqkvl= bf + OFF_WQKVL;
    __nv_bfloat16 *woh  = bf + OFF_WOH,  *wol  = bf + OFF_WOL;
    __nv_bfloat16 *w1h  = bf + OFF_W1H,  *w1l  = bf + OFF_W1L;
    __nv_bfloat16 *w2h  = bf + OFF_W2H,  *w2l  = bf + OFF_W2L;
    __nv_bfloat16 *wph  = bf + OFF_WPH,  *wpl  = bf + OFF_WPL;

    float* xo = (float*)d_out;
    float* pp = xo + NM;

    cudaFuncSetAttribute(gemm_mma, cudaFuncAttributeMaxDynamicSharedMemorySize, GEMM_SMEM);
    cudaFuncSetAttribute(flash_mma, cudaFuncAttributeMaxDynamicSharedMemorySize, FLASH_SMEM);

    dim3 tb(32, 8);
    // launch 0: batched D_xD_ transpose+split (Wq,Wk,Wv -> fused buffer; Wo)
    tsplit4_kernel<<<dim3(D_/32, D_/32, 4), tb>>>(
        Wq, Wk, Wv, Wo,
        wqkvh,          wqkvl,
        wqkvh + DD,     wqkvl + DD,
        wqkvh + 2*DD,   wqkvl + 2*DD,
        woh,            wol);
    // launch 1: bias concat
    biascat_kernel<<<QKVW/256, 256>>>(bq, bk, bv, bqkv);
    // launch 2: param_x split into cat cols [D_, D_+P_)
    {
        size_t tot = (size_t)MROWS * P_;
        split_kernel<<<(unsigned)((tot + 255) / 256), 256>>>(
            px, cath + D_, catl + D_, P_, CATW, tot);
    }
    // launch 3: xn = LN1(fx)
    ln_kernel<<<MROWS, 256>>>(fx, a1, be1, xn, xnh, xnl);
    // launch 4: W1 transpose+split (needed later; placed here so launch 5 = QKV)
    tsplit_kernel<<<dim3(DFF_/32, D_/32), tb>>>(W1, w1h, w1l, D_, DFF_);

    // launch 5 (ncu -s 5 target): fused QKV GEMM, N=3072
    gemm_mma<<<dim3(QKVW/128, MROWS/128), 256, GEMM_SMEM>>>(
        xnh, xnl, wqkvh, wqkvl, bqkv, nullptr, nullptr, qkvh, qkvl,
        MROWS, QKVW, D_, QKVW, 0);

    // launch 6: flash attention -> ctx hi/lo
    flash_mma<<<dim3(S_/128, B_*H_), 256, FLASH_SMEM>>>(qkvh, qkvl, ctxh, ctxl);

    // remaining weight preps
    tsplit_kernel<<<dim3(D_/32, DFF_/32), tb>>>(W2, w2h, w2l, DFF_, D_);
    tsplit_kernel<<<dim3(P_/32, CATW/32), tb>>>(Wp, wph, wpl, CATW, P_);

    // x1 = xn + ctx @ Wo + bo
    gemm_mma<<<dim3(D_/128, MROWS/128), 256, GEMM_SMEM>>>(
        ctxh, ctxl, woh, wol, bo, xn, x1, nullptr, nullptr, MROWS, D_, D_, 0, F_RESID);

    // x2 = LN2(x1)
    ln_kernel<<<MROWS, 256>>>(x1, a2, be2, x2, x2h, x2l);

    // hh = relu(x2 @ W1 + b1)
    gemm_mma<<<dim3(DFF_/128, MROWS/128), 256, GEMM_SMEM>>>(
        x2h, x2l, w1h, w1l, b1, nullptr, hh, hhh, hhl, MROWS, DFF_, D_, DFF_, F_RELU);

    // x = x1 + hh @ W2 + b2 -> d_out, + split into cat[:, 0:D]
    gemm_mma<<<dim3(D_/128, MROWS/128), 256, GEMM_SMEM>>>(
        hhh, hhl, w2h, w2l, b2, x1, xo, cath, catl, MROWS, D_, DFF_, CATW, F_RESID);

    // p = [x | px] @ Wp + bp  (single K=1280 GEMM)
    gemm_mma<<<dim3(P_/128, MROWS/128), 256, GEMM_SMEM>>>(
        cath, catl, wph, wpl, bp, nullptr, pp, nullptr, nullptr, MROWS, P_, CATW, 0, 0);
}